// round 11
// baseline (speedup 1.0000x reference)
#include <cuda_runtime.h>
#include <cuda_bf16.h>
#include <cuda_fp16.h>
#include <math.h>
#include <stdint.h>

#define B_   64
#define T_   512
#define IN_  128
#define H_   512
#define G4_  2048   // 4*H
#define OUT_ 128
#define M_   (B_ * T_)   // 32768

#define FBLK 128    // fused grid: 64 layer-0 + 64 layer-1 blocks
#define RTHR 256

// ---------------- scratch (static device memory; no allocs) ----------------
__device__ float g_xp[(size_t)M_ * G4_];            // layer-0 gate preactivations
__device__ unsigned int g_bars[64];                 // [0]=bar0 (L0), [32]=bar1 (L1)

__device__ __nv_bfloat16 g_Xhi[(size_t)M_ * IN_];   // x split (front GEMM, bf16x3)
__device__ __nv_bfloat16 g_Xlo[(size_t)M_ * IN_];
__device__ __nv_bfloat16 g_Whi[(size_t)G4_ * IN_];  // W_ih0 split
__device__ __nv_bfloat16 g_Wlo[(size_t)G4_ * IN_];
__device__ __half g_h0[4 * B_ * H_];                // layer-0 h, depth-4 ring (fp16)
__device__ __half g_h1[2 * B_ * H_];                // layer-1 h ping-pong (fp16)

// ======================= helpers ==============================
__device__ __forceinline__ uint32_t smem_u32(const void* p) {
    uint32_t a;
    asm("{ .reg .u64 t; cvta.to.shared.u64 t, %1; cvt.u32.u64 %0, t; }"
        : "=r"(a) : "l"(p));
    return a;
}

#define LDSM_X4(r, addr) \
    asm volatile("ldmatrix.sync.aligned.m8n8.x4.shared.b16 {%0,%1,%2,%3}, [%4];" \
        : "=r"((r)[0]), "=r"((r)[1]), "=r"((r)[2]), "=r"((r)[3]) : "r"(addr))
#define LDSM_X2(r, addr) \
    asm volatile("ldmatrix.sync.aligned.m8n8.x2.shared.b16 {%0,%1}, [%2];" \
        : "=r"((r)[0]), "=r"((r)[1]) : "r"(addr))

__device__ __forceinline__ void mma_bf16(float* d, const uint32_t* a, const uint32_t* b) {
    asm volatile("mma.sync.aligned.m16n8k16.row.col.f32.bf16.bf16.f32 "
        "{%0,%1,%2,%3}, {%4,%5,%6,%7}, {%8,%9}, {%0,%1,%2,%3};"
        : "+f"(d[0]), "+f"(d[1]), "+f"(d[2]), "+f"(d[3])
        : "r"(a[0]), "r"(a[1]), "r"(a[2]), "r"(a[3]), "r"(b[0]), "r"(b[1]));
}
__device__ __forceinline__ void mma_f16(float* d, const uint32_t* a, const uint32_t* b) {
    asm volatile("mma.sync.aligned.m16n8k16.row.col.f32.f16.f16.f32 "
        "{%0,%1,%2,%3}, {%4,%5,%6,%7}, {%8,%9}, {%0,%1,%2,%3};"
        : "+f"(d[0]), "+f"(d[1]), "+f"(d[2]), "+f"(d[3])
        : "r"(a[0]), "r"(a[1]), "r"(a[2]), "r"(a[3]), "r"(b[0]), "r"(b[1]));
}

#define CP_ASYNC16(dst, src) \
    asm volatile("cp.async.cg.shared.global [%0], [%1], 16;" :: "r"(dst), "l"(src))
#define CP_COMMIT() asm volatile("cp.async.commit_group;" ::: "memory")
#define CP_WAIT(n)  asm volatile("cp.async.wait_group %0;" :: "n"(n) : "memory")

__device__ __forceinline__ void spin_acq(unsigned* p, unsigned target) {
    unsigned v;
    do {
        asm volatile("ld.acquire.gpu.global.u32 %0, [%1];" : "=r"(v) : "l"(p) : "memory");
    } while (v < target);
}
__device__ __forceinline__ void rel_add(unsigned* p) {
    asm volatile("red.release.gpu.global.add.u32 [%0], %1;" :: "l"(p), "r"(1u) : "memory");
}

// ---------------------------------------------------------------------------
// fp32 -> (hi, lo) bf16 split; optionally resets the grid barrier counters
// ---------------------------------------------------------------------------
__global__ __launch_bounds__(256) void split_bf16_kernel(
    const float* __restrict__ in, __nv_bfloat16* __restrict__ hi,
    __nv_bfloat16* __restrict__ lo, int n, unsigned* bar_reset)
{
    if (bar_reset && blockIdx.x == 0 && threadIdx.x == 0) {
        bar_reset[0] = 0u; bar_reset[32] = 0u;
    }
    int i = blockIdx.x * 256 + threadIdx.x;
    if (i < n) {
        float v = in[i];
        __nv_bfloat16 h = __float2bfloat16(v);
        hi[i] = h;
        lo[i] = __float2bfloat16(v - __bfloat162float(h));
    }
}

// ---------------------------------------------------------------------------
// bf16x3 GEMM via mma.sync (layer-0 xp only; unchanged, passing since R3)
// ---------------------------------------------------------------------------
#define GSTRIDE 40
#define SMAT    (128 * GSTRIDE)
#define SSTAGE  (4 * SMAT)
#define GEMM_SMEM_BYTES (2 * SSTAGE * 2 + 128 * 4)

__global__ __launch_bounds__(256) void gemm_mma_kernel(
    const __nv_bfloat16* __restrict__ Ahi, const __nv_bfloat16* __restrict__ Alo,
    const __nv_bfloat16* __restrict__ Whi, const __nv_bfloat16* __restrict__ Wlo,
    const float* __restrict__ b1, const float* __restrict__ b2,
    float* __restrict__ C, int K)
{
    extern __shared__ __nv_bfloat16 sm[];
    float* biass = (float*)(sm + 2 * SSTAGE);

    const int tid  = threadIdx.x;
    const int wid  = tid >> 5;
    const int lane = tid & 31;
    const int wm   = wid >> 2;
    const int wn   = wid & 3;
    const int m0   = blockIdx.y * 128;
    const int n0   = blockIdx.x * 128;

    if (tid < 128) biass[tid] = b1[n0 + tid] + b2[n0 + tid];

    const int K8 = K >> 3;
    const uint4* gA[2] = { (const uint4*)Ahi, (const uint4*)Alo };
    const uint4* gW[2] = { (const uint4*)Whi, (const uint4*)Wlo };
    const uint32_t smb = smem_u32(sm);

    auto prefetch = [&](int kt, int st) {
        const int kk8 = kt * 4;
        const uint32_t sbase = smb + (uint32_t)st * (SSTAGE * 2);
#pragma unroll
        for (int hl = 0; hl < 2; hl++) {
#pragma unroll
            for (int i = 0; i < 2; i++) {
                int idx = tid + i * 256;
                int r = idx >> 2, j = idx & 3;
                uint32_t dst = sbase + (uint32_t)(hl * SMAT + r * GSTRIDE) * 2 + j * 16;
                CP_ASYNC16(dst, gA[hl] + (size_t)(m0 + r) * K8 + kk8 + j);
            }
#pragma unroll
            for (int i = 0; i < 2; i++) {
                int idx = tid + i * 256;
                int r = idx >> 2, j = idx & 3;
                uint32_t dst = sbase + (uint32_t)((2 + hl) * SMAT + r * GSTRIDE) * 2 + j * 16;
                CP_ASYNC16(dst, gW[hl] + (size_t)(n0 + r) * K8 + kk8 + j);
            }
        }
        CP_COMMIT();
    };

    float acc[4][4][4];
#pragma unroll
    for (int mi = 0; mi < 4; mi++)
#pragma unroll
        for (int ni = 0; ni < 4; ni++)
#pragma unroll
            for (int e = 0; e < 4; e++) acc[mi][ni][e] = 0.f;

    const int KT = K / 32;
    prefetch(0, 0);

    for (int kt = 0; kt < KT; kt++) {
        if (kt + 1 < KT) { prefetch(kt + 1, (kt + 1) & 1); CP_WAIT(1); }
        else             { CP_WAIT(0); }
        __syncthreads();

        const uint32_t sbase = smb + (uint32_t)(kt & 1) * (SSTAGE * 2);
#pragma unroll
        for (int ks = 0; ks < 2; ks++) {
            uint32_t aH[4][4], aL[4][4], bH[4][2], bL[4][2];

            const int arow = wm * 64 + (lane & 7) + ((lane >> 3) & 1) * 8;
            const int acol = ks * 16 + (lane >> 4) * 8;
#pragma unroll
            for (int mi = 0; mi < 4; mi++) {
                uint32_t ad = sbase + (uint32_t)((arow + mi * 16) * GSTRIDE + acol) * 2;
                LDSM_X4(aH[mi], ad);
                LDSM_X4(aL[mi], ad + SMAT * 2);
            }
            const int l16  = lane & 15;
            const int brow = wn * 32 + (l16 & 7);
            const int bcol = ks * 16 + (l16 >> 3) * 8;
#pragma unroll
            for (int ni = 0; ni < 4; ni++) {
                uint32_t bd = sbase + (uint32_t)(2 * SMAT + (brow + ni * 8) * GSTRIDE + bcol) * 2;
                LDSM_X2(bH[ni], bd);
                LDSM_X2(bL[ni], bd + SMAT * 2);
            }
#pragma unroll
            for (int mi = 0; mi < 4; mi++)
#pragma unroll
                for (int ni = 0; ni < 4; ni++) {
                    mma_bf16(acc[mi][ni], aH[mi], bH[ni]);
                    mma_bf16(acc[mi][ni], aH[mi], bL[ni]);
                    mma_bf16(acc[mi][ni], aL[mi], bH[ni]);
                }
        }
        __syncthreads();
    }

#pragma unroll
    for (int mi = 0; mi < 4; mi++) {
        const int r0 = m0 + wm * 64 + mi * 16 + (lane >> 2);
#pragma unroll
        for (int ni = 0; ni < 4; ni++) {
            const int c = wn * 32 + ni * 8 + (lane & 3) * 2;
            float2 v0, v1;
            v0.x = acc[mi][ni][0] + biass[c];
            v0.y = acc[mi][ni][1] + biass[c + 1];
            v1.x = acc[mi][ni][2] + biass[c];
            v1.y = acc[mi][ni][3] + biass[c + 1];
            *(float2*)&C[(size_t)r0 * G4_ + n0 + c]       = v0;
            *(float2*)&C[(size_t)(r0 + 8) * G4_ + n0 + c] = v1;
        }
    }
}

// ---------------------------------------------------------------------------
// FUSED two-layer persistent LSTM with DECOUPLED layer groups.
// Blocks 0..63 (L0): step t waits bar0>=t*64 (h0[t-1]) and bar1>=(t-3)*64
//   (WAR on depth-4 h0 ring), computes h0[t], releases bar0.
// Blocks 64..127 (L1): step t waits bar0>=(t+1)*64 (h0[t]), issues h0 loads,
//   then waits bar1>=t*64 (h1[t-1]), issues h1 loads; K=1024 matmul; h1[t];
//   releases bar1. L0 runs ahead; h0-load latency hides behind the bar1 wait.
// ---------------------------------------------------------------------------
// layer-0 SMEM layout
#define WS0_STR   520
#define HS0_OFF   33280u            // 32*520*2
#define HC_BYTES  17408u            // 64*136*2 per 128-col chunk
#define XS0_OFF   102912u           // HS0_OFF + 4*HC_BYTES
#define GS0_OFF   111104u
#define CS0_OFF   119552u
// layer-1 SMEM layout
#define WS1_STR   1048
#define HS1_OFF   67072u            // 8 chunk slots (h0: 0..3, h1: 4..7)
#define GS1_OFF   206336u           // HS1_OFF + 8*HC_BYTES
#define CS1_OFF   214784u
#define BS1_OFF   216832u
#define FUSED_SMEM 217088

__global__ __launch_bounds__(RTHR, 1) void lstm_fused_kernel(
    const float* __restrict__ xp0, const float* __restrict__ Whh0,
    const float* __restrict__ Wih1, const float* __restrict__ Whh1,
    const float* __restrict__ b_ih1, const float* __restrict__ b_hh1,
    __half* __restrict__ h0, __half* __restrict__ h1,
    unsigned* __restrict__ bars)
{
    extern __shared__ char sm8[];
    const int tx   = threadIdx.x;
    const int wid  = tx >> 5;
    const int lane = tx & 31;
    const int mw   = wid >> 1;           // 0..3  (M16 of 64 batch rows)
    const int nw   = wid & 1;            // 0..1  (N16 of 32 gate cols)
    const bool isL0 = blockIdx.x < 64;
    const int j0   = (blockIdx.x & 63) * 8;

    unsigned* bar0 = bars;
    unsigned* bar1 = bars + 32;

    const uint32_t smb = smem_u32(sm8);
    __half* ws = (__half*)sm8;

    // fragment addressing helpers
    const int arow_l = (lane & 7) + ((lane >> 3) & 1) * 8;   // + mw*16
    const int acol_l = (lane >> 4) * 8;
    const int brow_l = ((lane >> 4) & 1) * 8 + (lane & 7);   // + nw*16
    const int bcol_l = ((lane >> 3) & 1) * 8;

    if (isL0) {
        // ---- layer-0 setup: W_hh0 slice -> fp16 (stride 520) ----
#pragma unroll 4
        for (int i = 0; i < 64; i++) {
            int idx = tx + i * 256;
            int cc = idx >> 9, k = idx & 511;
            int gg = cc >> 3, u = cc & 7;
            ws[cc * WS0_STR + k] =
                __float2half(Whh0[(size_t)(gg * H_ + j0 + u) * H_ + k]);
        }
    } else {
        // ---- layer-1 setup: [W_ih1 ; W_hh1] slice -> fp16 (stride 1048) ----
#pragma unroll 4
        for (int i = 0; i < 128; i++) {
            int idx = tx + i * 256;
            int cc = idx >> 10, k = idx & 1023;
            int gg = cc >> 3, u = cc & 7;
            size_t row = (size_t)(gg * H_ + j0 + u) * H_;
            float w = (k < 512) ? Wih1[row + k] : Whh1[row + k - 512];
            ws[cc * WS1_STR + k] = __float2half(w);
        }
        if (tx < 32) {
            int gg = tx >> 3, u = tx & 7;
            ((float*)(sm8 + BS1_OFF))[tx] =
                b_ih1[gg * H_ + j0 + u] + b_hh1[gg * H_ + j0 + u];
        }
    }
    __syncthreads();

    float acc[2][4];

    if (isL0) {
        float* xs = (float*)(sm8 + XS0_OFF);
        float* gs = (float*)(sm8 + GS0_OFF);
        float* cs = (float*)(sm8 + CS0_OFF);
        const uint32_t hsb = smb + HS0_OFF;

        for (int t = 0; t < T_; t++) {
            if (t > 0) {
                if (tx == 0) {
                    spin_acq(bar0, (unsigned)t * 64u);
                    if (t >= 4) spin_acq(bar1, (unsigned)(t - 3) * 64u);
                }
                __syncthreads();
            }

            // issue xp tile + 4 h0[t-1] chunks, single commit group
#pragma unroll
            for (int i = 0; i < 2; i++) {
                int idx = tx + i * 256;
                int b = idx >> 3, gg = (idx >> 1) & 3, seg = idx & 1;
                uint32_t dst = smb + XS0_OFF + (uint32_t)(b * 32 + gg * 8 + seg * 4) * 4;
                CP_ASYNC16(dst, xp0 + ((size_t)b * T_ + t) * G4_ + gg * H_ + j0 + seg * 4);
            }
            if (t > 0) {
                const long long inoff = (long long)((t - 1) & 3) * B_ * H_;
#pragma unroll
                for (int c = 0; c < 4; c++) {
#pragma unroll
                    for (int i = 0; i < 4; i++) {
                        int idx = tx + i * 256;
                        int r   = idx >> 4;
                        int seg = idx & 15;
                        const __half* src = h0 + inoff + (long long)r * H_ + c * 128 + seg * 8;
                        uint32_t dst = hsb + (uint32_t)c * HC_BYTES
                                     + (uint32_t)(r * 136 + seg * 8) * 2;
                        CP_ASYNC16(dst, src);
                    }
                }
            }
            CP_COMMIT();
            CP_WAIT(0);
            __syncthreads();

            if (t > 0) {
#pragma unroll
                for (int ni = 0; ni < 2; ni++)
#pragma unroll
                    for (int e = 0; e < 4; e++) acc[ni][e] = 0.f;
#pragma unroll
                for (int c = 0; c < 4; c++) {
                    const uint32_t hb = hsb + (uint32_t)c * HC_BYTES;
#pragma unroll
                    for (int kk2 = 0; kk2 < 8; kk2++) {
                        uint32_t a[4], bf[4];
                        uint32_t ad = hb + (uint32_t)((mw * 16 + arow_l) * 136
                                                      + kk2 * 16 + acol_l) * 2;
                        LDSM_X4(a, ad);
                        int kg = c * 8 + kk2;
                        uint32_t bd = smb + (uint32_t)((nw * 16 + brow_l) * WS0_STR
                                                       + kg * 16 + bcol_l) * 2;
                        LDSM_X4(bf, bd);
                        mma_f16(acc[0], a, bf);
                        mma_f16(acc[1], a, bf + 2);
                    }
                }
#pragma unroll
                for (int ni = 0; ni < 2; ni++) {
                    int r = mw * 16 + (lane >> 2);
                    int cb = nw * 16 + ni * 8 + (lane & 3) * 2;
                    gs[r * 33 + cb]           = acc[ni][0];
                    gs[r * 33 + cb + 1]       = acc[ni][1];
                    gs[(r + 8) * 33 + cb]     = acc[ni][2];
                    gs[(r + 8) * 33 + cb + 1] = acc[ni][3];
                }
                __syncthreads();
            }

            const long long outoff = (long long)(t & 3) * B_ * H_;
#pragma unroll
            for (int i = 0; i < 2; i++) {
                int e = tx + i * 256;
                int b = e >> 3, u = e & 7;
                float gi = xs[b * 32 + 0 * 8 + u];
                float gf = xs[b * 32 + 1 * 8 + u];
                float gc = xs[b * 32 + 2 * 8 + u];
                float go = xs[b * 32 + 3 * 8 + u];
                if (t > 0) {
                    gi += gs[b * 33 + 0 * 8 + u];
                    gf += gs[b * 33 + 1 * 8 + u];
                    gc += gs[b * 33 + 2 * 8 + u];
                    go += gs[b * 33 + 3 * 8 + u];
                }
                float i_ = 1.f / (1.f + expf(-gi));
                float f_ = 1.f / (1.f + expf(-gf));
                float g_ = tanhf(gc);
                float o_ = 1.f / (1.f + expf(-go));
                float cold = (t == 0) ? 0.f : cs[e];
                float cn = f_ * cold + i_ * g_;
                cs[e] = cn;
                h0[outoff + (long long)b * H_ + j0 + u] = __float2half(o_ * tanhf(cn));
            }
            __syncthreads();
            if (tx == 0) rel_add(bar0);
        }
    } else {
        float* gs = (float*)(sm8 + GS1_OFF);
        float* cs = (float*)(sm8 + CS1_OFF);
        float* bs = (float*)(sm8 + BS1_OFF);
        const uint32_t hsb = smb + HS1_OFF;

        for (int t = 0; t < T_; t++) {
            // h0[t] ready?
            if (tx == 0) spin_acq(bar0, (unsigned)(t + 1) * 64u);
            __syncthreads();

            // issue 4 h0[t] chunks (slots 0..3)
            {
                const long long in0 = (long long)(t & 3) * B_ * H_;
#pragma unroll
                for (int c = 0; c < 4; c++) {
#pragma unroll
                    for (int i = 0; i < 4; i++) {
                        int idx = tx + i * 256;
                        int r   = idx >> 4;
                        int seg = idx & 15;
                        const __half* src = h0 + in0 + (long long)r * H_ + c * 128 + seg * 8;
                        uint32_t dst = hsb + (uint32_t)c * HC_BYTES
                                     + (uint32_t)(r * 136 + seg * 8) * 2;
                        CP_ASYNC16(dst, src);
                    }
                }
                CP_COMMIT();
            }

            if (t > 0) {
                // h1[t-1] ready? (the on-chain wait; h0 loads fly meanwhile)
                if (tx == 0) spin_acq(bar1, (unsigned)t * 64u);
                __syncthreads();
                const long long in1 = (long long)((t - 1) & 1) * B_ * H_;
#pragma unroll
                for (int c = 0; c < 4; c++) {
#pragma unroll
                    for (int i = 0; i < 4; i++) {
                        int idx = tx + i * 256;
                        int r   = idx >> 4;
                        int seg = idx & 15;
                        const __half* src = h1 + in1 + (long long)r * H_ + c * 128 + seg * 8;
                        uint32_t dst = hsb + (uint32_t)(4 + c) * HC_BYTES
                                     + (uint32_t)(r * 136 + seg * 8) * 2;
                        CP_ASYNC16(dst, src);
                    }
                }
                CP_COMMIT();
            }
            CP_WAIT(0);
            __syncthreads();

#pragma unroll
            for (int ni = 0; ni < 2; ni++)
#pragma unroll
                for (int e = 0; e < 4; e++) acc[ni][e] = 0.f;

            const int nch = (t == 0) ? 4 : 8;
            for (int c = 0; c < nch; c++) {
                const uint32_t hb = hsb + (uint32_t)c * HC_BYTES;
#pragma unroll
                for (int kk2 = 0; kk2 < 8; kk2++) {
                    uint32_t a[4], bf[4];
                    uint32_t ad = hb + (uint32_t)((mw * 16 + arow_l) * 136
                                                  + kk2 * 16 + acol_l) * 2;
                    LDSM_X4(a, ad);
                    int kg = c * 8 + kk2;            // 0..63 over concat K
                    uint32_t bd = smb + (uint32_t)((nw * 16 + brow_l) * WS1_STR
                                                   + kg * 16 + bcol_l) * 2;
                    LDSM_X4(bf, bd);
                    mma_f16(acc[0], a, bf);
                    mma_f16(acc[1], a, bf + 2);
                }
            }

#pragma unroll
            for (int ni = 0; ni < 2; ni++) {
                int r = mw * 16 + (lane >> 2);
                int cb = nw * 16 + ni * 8 + (lane & 3) * 2;
                gs[r * 33 + cb]           = acc[ni][0];
                gs[r * 33 + cb + 1]       = acc[ni][1];
                gs[(r + 8) * 33 + cb]     = acc[ni][2];
                gs[(r + 8) * 33 + cb + 1] = acc[ni][3];
            }
            __syncthreads();

            const long long outoff = (long long)(t & 1) * B_ * H_;
#pragma unroll
            for (int i = 0; i < 2; i++) {
                int e = tx + i * 256;
                int b = e >> 3, u = e & 7;
                float gi = bs[0 * 8 + u] + gs[b * 33 + 0 * 8 + u];
                float gf = bs[1 * 8 + u] + gs[b * 33 + 1 * 8 + u];
                float gc = bs[2 * 8 + u] + gs[b * 33 + 2 * 8 + u];
                float go = bs[3 * 8 + u] + gs[b * 33 + 3 * 8 + u];
                float i_ = 1.f / (1.f + expf(-gi));
                float f_ = 1.f / (1.f + expf(-gf));
                float g_ = tanhf(gc);
                float o_ = 1.f / (1.f + expf(-go));
                float cold = (t == 0) ? 0.f : cs[e];
                float cn = f_ * cold + i_ * g_;
                cs[e] = cn;
                h1[outoff + (long long)b * H_ + j0 + u] = __float2half(o_ * tanhf(cn));
            }
            __syncthreads();
            if (tx == 0) rel_add(bar1);
        }
    }
}

// ---------------------------------------------------------------------------
// Final FC on fp16 h
// ---------------------------------------------------------------------------
__global__ __launch_bounds__(128) void fc_kernel(
    const __half* __restrict__ h, const float* __restrict__ Wfc,
    const float* __restrict__ bfc, float* __restrict__ out)
{
    __shared__ float hrow[H_];
    int b = blockIdx.x;
    for (int k = threadIdx.x; k < H_; k += 128)
        hrow[k] = __half2float(h[b * H_ + k]);
    __syncthreads();

    int o = threadIdx.x;
    float s = bfc[o];
    const float4* w4 = reinterpret_cast<const float4*>(Wfc + (size_t)o * H_);
    const float4* h4 = reinterpret_cast<const float4*>(hrow);
#pragma unroll 4
    for (int k = 0; k < H_ / 4; k++) {
        float4 w = w4[k];
        float4 hh = h4[k];
        s += w.x * hh.x + w.y * hh.y + w.z * hh.z + w.w * hh.w;
    }
    out[b * OUT_ + o] = s;
}

// ---------------------------------------------------------------------------
extern "C" void kernel_launch(void* const* d_in, const int* in_sizes, int n_in,
                              void* d_out, int out_size)
{
    const float* x     = (const float*)d_in[0];
    const float* W_ih0 = (const float*)d_in[1];
    const float* W_hh0 = (const float*)d_in[2];
    const float* b_ih0 = (const float*)d_in[3];
    const float* b_hh0 = (const float*)d_in[4];
    const float* W_ih1 = (const float*)d_in[5];
    const float* W_hh1 = (const float*)d_in[6];
    const float* b_ih1 = (const float*)d_in[7];
    const float* b_hh1 = (const float*)d_in[8];
    const float* W_fc  = (const float*)d_in[9];
    const float* b_fc  = (const float*)d_in[10];
    float* out = (float*)d_out;

    float* xp;
    unsigned* bars;
    __nv_bfloat16 *xhi, *xlo, *whi, *wlo;
    __half *h0, *h1;
    cudaGetSymbolAddress((void**)&xp,   g_xp);
    cudaGetSymbolAddress((void**)&bars, g_bars);
    cudaGetSymbolAddress((void**)&xhi,  g_Xhi);
    cudaGetSymbolAddress((void**)&xlo,  g_Xlo);
    cudaGetSymbolAddress((void**)&whi,  g_Whi);
    cudaGetSymbolAddress((void**)&wlo,  g_Wlo);
    cudaGetSymbolAddress((void**)&h0,   g_h0);
    cudaGetSymbolAddress((void**)&h1,   g_h1);

    cudaFuncSetAttribute(gemm_mma_kernel,
                         cudaFuncAttributeMaxDynamicSharedMemorySize, GEMM_SMEM_BYTES);
    cudaFuncSetAttribute(lstm_fused_kernel,
                         cudaFuncAttributeMaxDynamicSharedMemorySize, FUSED_SMEM);

    dim3 mma_grid(G4_ / 128, M_ / 128);   // (16, 256)

    // layer-0 xp GEMM (K=128); first split also resets the barrier counters
    {
        int nA = M_ * IN_;
        int nW = G4_ * IN_;
        split_bf16_kernel<<<(nA + 255) / 256, 256>>>(x, xhi, xlo, nA, bars);
        split_bf16_kernel<<<(nW + 255) / 256, 256>>>(W_ih0, whi, wlo, nW, nullptr);
        gemm_mma_kernel<<<mma_grid, 256, GEMM_SMEM_BYTES>>>(xhi, xlo, whi, wlo,
                                                            b_ih0, b_hh0, xp, IN_);
    }

    // fused two-layer recurrence (decoupled barrier chains)
    lstm_fused_kernel<<<FBLK, RTHR, FUSED_SMEM>>>(
        xp, W_hh0, W_ih1, W_hh1, b_ih1, b_hh1, h0, h1, bars);

    // final FC on h1[t=511] (parity 1)
    fc_kernel<<<B_, 128>>>(h1 + (size_t)B_ * H_, W_fc, b_fc, out);
}

// round 12
// speedup vs baseline: 1.1361x; 1.1361x over previous
#include <cuda_runtime.h>
#include <cuda_bf16.h>
#include <cuda_fp16.h>
#include <math.h>
#include <stdint.h>

#define B_   64
#define T_   512
#define IN_  128
#define H_   512
#define G4_  2048   // 4*H
#define OUT_ 128
#define M_   (B_ * T_)   // 32768

#define FBLK 128    // fused grid: 64 layer-0 + 64 layer-1 blocks
#define RTHR 256

// ---------------- scratch (static device memory; no allocs) ----------------
__device__ float g_xp[(size_t)M_ * G4_];            // layer-0 gate preactivations
__device__ unsigned int g_bar;                      // grid barrier counter

__device__ __nv_bfloat16 g_Xhi[(size_t)M_ * IN_];   // x split (front GEMM, bf16x3)
__device__ __nv_bfloat16 g_Xlo[(size_t)M_ * IN_];
__device__ __nv_bfloat16 g_Whi[(size_t)G4_ * IN_];  // W_ih0 split
__device__ __nv_bfloat16 g_Wlo[(size_t)G4_ * IN_];
__device__ __half g_h0[2 * B_ * H_];                // layer-0 h ping-pong (fp16)
__device__ __half g_h1[2 * B_ * H_];                // layer-1 h ping-pong (fp16)

// ======================= helpers ==============================
__device__ __forceinline__ uint32_t smem_u32(const void* p) {
    uint32_t a;
    asm("{ .reg .u64 t; cvta.to.shared.u64 t, %1; cvt.u32.u64 %0, t; }"
        : "=r"(a) : "l"(p));
    return a;
}

#define LDSM_X4(r, addr) \
    asm volatile("ldmatrix.sync.aligned.m8n8.x4.shared.b16 {%0,%1,%2,%3}, [%4];" \
        : "=r"((r)[0]), "=r"((r)[1]), "=r"((r)[2]), "=r"((r)[3]) : "r"(addr))
#define LDSM_X2(r, addr) \
    asm volatile("ldmatrix.sync.aligned.m8n8.x2.shared.b16 {%0,%1}, [%2];" \
        : "=r"((r)[0]), "=r"((r)[1]) : "r"(addr))

__device__ __forceinline__ void mma_bf16(float* d, const uint32_t* a, const uint32_t* b) {
    asm volatile("mma.sync.aligned.m16n8k16.row.col.f32.bf16.bf16.f32 "
        "{%0,%1,%2,%3}, {%4,%5,%6,%7}, {%8,%9}, {%0,%1,%2,%3};"
        : "+f"(d[0]), "+f"(d[1]), "+f"(d[2]), "+f"(d[3])
        : "r"(a[0]), "r"(a[1]), "r"(a[2]), "r"(a[3]), "r"(b[0]), "r"(b[1]));
}
__device__ __forceinline__ void mma_f16(float* d, const uint32_t* a, const uint32_t* b) {
    asm volatile("mma.sync.aligned.m16n8k16.row.col.f32.f16.f16.f32 "
        "{%0,%1,%2,%3}, {%4,%5,%6,%7}, {%8,%9}, {%0,%1,%2,%3};"
        : "+f"(d[0]), "+f"(d[1]), "+f"(d[2]), "+f"(d[3])
        : "r"(a[0]), "r"(a[1]), "r"(a[2]), "r"(a[3]), "r"(b[0]), "r"(b[1]));
}

#define CP_ASYNC16(dst, src) \
    asm volatile("cp.async.cg.shared.global [%0], [%1], 16;" :: "r"(dst), "l"(src))
#define CP_COMMIT() asm volatile("cp.async.commit_group;" ::: "memory")
#define CP_WAIT(n)  asm volatile("cp.async.wait_group %0;" :: "n"(n) : "memory")

// ---------------------------------------------------------------------------
// fp32 -> (hi, lo) bf16 split; optionally resets the grid barrier counter
// ---------------------------------------------------------------------------
__global__ __launch_bounds__(256) void split_bf16_kernel(
    const float* __restrict__ in, __nv_bfloat16* __restrict__ hi,
    __nv_bfloat16* __restrict__ lo, int n, unsigned* bar_reset)
{
    if (bar_reset && blockIdx.x == 0 && threadIdx.x == 0) *bar_reset = 0u;
    int i = blockIdx.x * 256 + threadIdx.x;
    if (i < n) {
        float v = in[i];
        __nv_bfloat16 h = __float2bfloat16(v);
        hi[i] = h;
        lo[i] = __float2bfloat16(v - __bfloat162float(h));
    }
}

// ---------------------------------------------------------------------------
// bf16x3 GEMM via mma.sync (layer-0 xp only; unchanged, passing since R3)
// ---------------------------------------------------------------------------
#define GSTRIDE 40
#define SMAT    (128 * GSTRIDE)
#define SSTAGE  (4 * SMAT)
#define GEMM_SMEM_BYTES (2 * SSTAGE * 2 + 128 * 4)

__global__ __launch_bounds__(256) void gemm_mma_kernel(
    const __nv_bfloat16* __restrict__ Ahi, const __nv_bfloat16* __restrict__ Alo,
    const __nv_bfloat16* __restrict__ Whi, const __nv_bfloat16* __restrict__ Wlo,
    const float* __restrict__ b1, const float* __restrict__ b2,
    float* __restrict__ C, int K)
{
    extern __shared__ __nv_bfloat16 sm[];
    float* biass = (float*)(sm + 2 * SSTAGE);

    const int tid  = threadIdx.x;
    const int wid  = tid >> 5;
    const int lane = tid & 31;
    const int wm   = wid >> 2;
    const int wn   = wid & 3;
    const int m0   = blockIdx.y * 128;
    const int n0   = blockIdx.x * 128;

    if (tid < 128) biass[tid] = b1[n0 + tid] + b2[n0 + tid];

    const int K8 = K >> 3;
    const uint4* gA[2] = { (const uint4*)Ahi, (const uint4*)Alo };
    const uint4* gW[2] = { (const uint4*)Whi, (const uint4*)Wlo };
    const uint32_t smb = smem_u32(sm);

    auto prefetch = [&](int kt, int st) {
        const int kk8 = kt * 4;
        const uint32_t sbase = smb + (uint32_t)st * (SSTAGE * 2);
#pragma unroll
        for (int hl = 0; hl < 2; hl++) {
#pragma unroll
            for (int i = 0; i < 2; i++) {
                int idx = tid + i * 256;
                int r = idx >> 2, j = idx & 3;
                uint32_t dst = sbase + (uint32_t)(hl * SMAT + r * GSTRIDE) * 2 + j * 16;
                CP_ASYNC16(dst, gA[hl] + (size_t)(m0 + r) * K8 + kk8 + j);
            }
#pragma unroll
            for (int i = 0; i < 2; i++) {
                int idx = tid + i * 256;
                int r = idx >> 2, j = idx & 3;
                uint32_t dst = sbase + (uint32_t)((2 + hl) * SMAT + r * GSTRIDE) * 2 + j * 16;
                CP_ASYNC16(dst, gW[hl] + (size_t)(n0 + r) * K8 + kk8 + j);
            }
        }
        CP_COMMIT();
    };

    float acc[4][4][4];
#pragma unroll
    for (int mi = 0; mi < 4; mi++)
#pragma unroll
        for (int ni = 0; ni < 4; ni++)
#pragma unroll
            for (int e = 0; e < 4; e++) acc[mi][ni][e] = 0.f;

    const int KT = K / 32;
    prefetch(0, 0);

    for (int kt = 0; kt < KT; kt++) {
        if (kt + 1 < KT) { prefetch(kt + 1, (kt + 1) & 1); CP_WAIT(1); }
        else             { CP_WAIT(0); }
        __syncthreads();

        const uint32_t sbase = smb + (uint32_t)(kt & 1) * (SSTAGE * 2);
#pragma unroll
        for (int ks = 0; ks < 2; ks++) {
            uint32_t aH[4][4], aL[4][4], bH[4][2], bL[4][2];

            const int arow = wm * 64 + (lane & 7) + ((lane >> 3) & 1) * 8;
            const int acol = ks * 16 + (lane >> 4) * 8;
#pragma unroll
            for (int mi = 0; mi < 4; mi++) {
                uint32_t ad = sbase + (uint32_t)((arow + mi * 16) * GSTRIDE + acol) * 2;
                LDSM_X4(aH[mi], ad);
                LDSM_X4(aL[mi], ad + SMAT * 2);
            }
            const int l16  = lane & 15;
            const int brow = wn * 32 + (l16 & 7);
            const int bcol = ks * 16 + (l16 >> 3) * 8;
#pragma unroll
            for (int ni = 0; ni < 4; ni++) {
                uint32_t bd = sbase + (uint32_t)(2 * SMAT + (brow + ni * 8) * GSTRIDE + bcol) * 2;
                LDSM_X2(bH[ni], bd);
                LDSM_X2(bL[ni], bd + SMAT * 2);
            }
#pragma unroll
            for (int mi = 0; mi < 4; mi++)
#pragma unroll
                for (int ni = 0; ni < 4; ni++) {
                    mma_bf16(acc[mi][ni], aH[mi], bH[ni]);
                    mma_bf16(acc[mi][ni], aH[mi], bL[ni]);
                    mma_bf16(acc[mi][ni], aL[mi], bH[ni]);
                }
        }
        __syncthreads();
    }

#pragma unroll
    for (int mi = 0; mi < 4; mi++) {
        const int r0 = m0 + wm * 64 + mi * 16 + (lane >> 2);
#pragma unroll
        for (int ni = 0; ni < 4; ni++) {
            const int c = wn * 32 + ni * 8 + (lane & 3) * 2;
            float2 v0, v1;
            v0.x = acc[mi][ni][0] + biass[c];
            v0.y = acc[mi][ni][1] + biass[c + 1];
            v1.x = acc[mi][ni][2] + biass[c];
            v1.y = acc[mi][ni][3] + biass[c + 1];
            *(float2*)&C[(size_t)r0 * G4_ + n0 + c]       = v0;
            *(float2*)&C[(size_t)(r0 + 8) * G4_ + n0 + c] = v1;
        }
    }
}

// ---------------------------------------------------------------------------
// FUSED two-layer persistent LSTM, pure fp16, lockstep barrier (R9 base).
// L1 change vs R9: all 8 K-chunks (h0[t] ; h1[t-1]) staged in SMEM, loads all
// issued at stage start (8 commit groups), staggered CP_WAIT(7..0) — only the
// first chunk's L2 latency is exposed; the rest stream behind compute.
// ---------------------------------------------------------------------------
// layer-0 SMEM layout
#define WS0_STR   520
#define HS0_OFF   33280u            // 32*520*2
#define HC_BYTES  17408u            // 64*136*2 per 128-col chunk
#define XS0_OFF   102912u           // HS0_OFF + 4*HC_BYTES
#define GS0_OFF   111104u
#define CS0_OFF   119552u
// layer-1 SMEM layout
#define WS1_STR   1048
#define HS1_OFF   67072u            // 8 chunk slots (h0: 0..3, h1: 4..7)
#define GS1_OFF   206336u           // HS1_OFF + 8*HC_BYTES
#define CS1_OFF   214784u
#define BS1_OFF   216832u
#define FUSED_SMEM 217088

__global__ __launch_bounds__(RTHR, 1) void lstm_fused_kernel(
    const float* __restrict__ xp0, const float* __restrict__ Whh0,
    const float* __restrict__ Wih1, const float* __restrict__ Whh1,
    const float* __restrict__ b_ih1, const float* __restrict__ b_hh1,
    __half* __restrict__ h0, __half* __restrict__ h1,
    unsigned* __restrict__ bar)
{
    extern __shared__ char sm8[];
    const int tx   = threadIdx.x;
    const int wid  = tx >> 5;
    const int lane = tx & 31;
    const int mw   = wid >> 1;           // 0..3  (M16 of 64 batch rows)
    const int nw   = wid & 1;            // 0..1  (N16 of 32 gate cols)
    const bool isL0 = blockIdx.x < 64;
    const int j0   = (blockIdx.x & 63) * 8;

    const uint32_t smb = smem_u32(sm8);
    __half* ws = (__half*)sm8;

    // fragment addressing helpers
    const int arow_l = (lane & 7) + ((lane >> 3) & 1) * 8;   // + mw*16
    const int acol_l = (lane >> 4) * 8;
    const int brow_l = ((lane >> 4) & 1) * 8 + (lane & 7);   // + nw*16
    const int bcol_l = ((lane >> 3) & 1) * 8;

    if (isL0) {
        // ---- layer-0 setup: W_hh0 slice -> fp16 (stride 520) ----
#pragma unroll 4
        for (int i = 0; i < 64; i++) {
            int idx = tx + i * 256;
            int cc = idx >> 9, k = idx & 511;
            int gg = cc >> 3, u = cc & 7;
            ws[cc * WS0_STR + k] =
                __float2half(Whh0[(size_t)(gg * H_ + j0 + u) * H_ + k]);
        }
    } else {
        // ---- layer-1 setup: [W_ih1 ; W_hh1] slice -> fp16 (stride 1048) ----
#pragma unroll 4
        for (int i = 0; i < 128; i++) {
            int idx = tx + i * 256;
            int cc = idx >> 10, k = idx & 1023;
            int gg = cc >> 3, u = cc & 7;
            size_t row = (size_t)(gg * H_ + j0 + u) * H_;
            float w = (k < 512) ? Wih1[row + k] : Whh1[row + k - 512];
            ws[cc * WS1_STR + k] = __float2half(w);
        }
        if (tx < 32) {
            int gg = tx >> 3, u = tx & 7;
            ((float*)(sm8 + BS1_OFF))[tx] =
                b_ih1[gg * H_ + j0 + u] + b_hh1[gg * H_ + j0 + u];
        }
    }
    __syncthreads();

    float acc[2][4];

    for (int s = 0; s <= T_; s++) {
        if (isL0 && s < T_) {
            // ================= layer-0 step s =================
            const int t = s;
            float* xs = (float*)(sm8 + XS0_OFF);
            float* gs = (float*)(sm8 + GS0_OFF);
            float* cs = (float*)(sm8 + CS0_OFF);
            const uint32_t hsb = smb + HS0_OFF;

            // group 0: xp tile
#pragma unroll
            for (int i = 0; i < 2; i++) {
                int idx = tx + i * 256;
                int b = idx >> 3, gg = (idx >> 1) & 3, seg = idx & 1;
                uint32_t dst = smb + XS0_OFF + (uint32_t)(b * 32 + gg * 8 + seg * 4) * 4;
                CP_ASYNC16(dst, xp0 + ((size_t)b * T_ + t) * G4_ + gg * H_ + j0 + seg * 4);
            }
            CP_COMMIT();

#pragma unroll
            for (int ni = 0; ni < 2; ni++)
#pragma unroll
                for (int e = 0; e < 4; e++) acc[ni][e] = 0.f;

            if (t > 0) {
                const long long inoff = (long long)((t & 1) ^ 1) * B_ * H_;
                // groups 1..4: four 128-col chunks of h0 (fp16)
#pragma unroll
                for (int c = 0; c < 4; c++) {
#pragma unroll
                    for (int i = 0; i < 4; i++) {
                        int idx = tx + i * 256;
                        int r   = idx >> 4;
                        int seg = idx & 15;
                        const __half* src = h0 + inoff + (long long)r * H_ + c * 128 + seg * 8;
                        uint32_t dst = hsb + (uint32_t)c * HC_BYTES
                                     + (uint32_t)(r * 136 + seg * 8) * 2;
                        CP_ASYNC16(dst, src);
                    }
                    CP_COMMIT();
                }

                auto consume = [&](int c) {
                    const uint32_t hb = hsb + (uint32_t)c * HC_BYTES;
#pragma unroll
                    for (int kk2 = 0; kk2 < 8; kk2++) {
                        uint32_t a[4], bf[4];
                        uint32_t ad = hb + (uint32_t)((mw * 16 + arow_l) * 136
                                                      + kk2 * 16 + acol_l) * 2;
                        LDSM_X4(a, ad);
                        int kg = c * 8 + kk2;
                        uint32_t bd = smb + (uint32_t)((nw * 16 + brow_l) * WS0_STR
                                                       + kg * 16 + bcol_l) * 2;
                        LDSM_X4(bf, bd);
                        mma_f16(acc[0], a, bf);
                        mma_f16(acc[1], a, bf + 2);
                    }
                };
                CP_WAIT(3); __syncthreads(); consume(0);
                CP_WAIT(2); __syncthreads(); consume(1);
                CP_WAIT(1); __syncthreads(); consume(2);
                CP_WAIT(0); __syncthreads(); consume(3);

#pragma unroll
                for (int ni = 0; ni < 2; ni++) {
                    int r = mw * 16 + (lane >> 2);
                    int cb = nw * 16 + ni * 8 + (lane & 3) * 2;
                    gs[r * 33 + cb]           = acc[ni][0];
                    gs[r * 33 + cb + 1]       = acc[ni][1];
                    gs[(r + 8) * 33 + cb]     = acc[ni][2];
                    gs[(r + 8) * 33 + cb + 1] = acc[ni][3];
                }
            } else {
                CP_WAIT(0);
            }
            __syncthreads();

            const long long outoff = (long long)(t & 1) * B_ * H_;
#pragma unroll
            for (int i = 0; i < 2; i++) {
                int e = tx + i * 256;
                int b = e >> 3, u = e & 7;
                float gi = xs[b * 32 + 0 * 8 + u];
                float gf = xs[b * 32 + 1 * 8 + u];
                float gc = xs[b * 32 + 2 * 8 + u];
                float go = xs[b * 32 + 3 * 8 + u];
                if (t > 0) {
                    gi += gs[b * 33 + 0 * 8 + u];
                    gf += gs[b * 33 + 1 * 8 + u];
                    gc += gs[b * 33 + 2 * 8 + u];
                    go += gs[b * 33 + 3 * 8 + u];
                }
                float i_ = 1.f / (1.f + expf(-gi));
                float f_ = 1.f / (1.f + expf(-gf));
                float g_ = tanhf(gc);
                float o_ = 1.f / (1.f + expf(-go));
                float cold = (t == 0) ? 0.f : cs[e];
                float cn = f_ * cold + i_ * g_;
                cs[e] = cn;
                h0[outoff + (long long)b * H_ + j0 + u] = __float2half(o_ * tanhf(cn));
            }
        } else if (!isL0 && s >= 1) {
            // ================= layer-1 step t = s-1 =================
            const int t = s - 1;
            float* gs = (float*)(sm8 + GS1_OFF);
            float* cs = (float*)(sm8 + CS1_OFF);
            float* bs = (float*)(sm8 + BS1_OFF);
            const uint32_t hsb = smb + HS1_OFF;

#pragma unroll
            for (int ni = 0; ni < 2; ni++)
#pragma unroll
                for (int e = 0; e < 4; e++) acc[ni][e] = 0.f;

            const long long in0 = (long long)(t & 1) * B_ * H_;         // h0[t]
            const long long in1 = (long long)((t & 1) ^ 1) * B_ * H_;   // h1[t-1]

            auto issue = [&](int kc) {
                const __half* sh;
                int coff;
                if (kc < 4) { sh = h0 + in0; coff = kc * 128; }
                else        { sh = h1 + in1; coff = (kc - 4) * 128; }
#pragma unroll
                for (int i = 0; i < 4; i++) {
                    int idx = tx + i * 256;
                    int r   = idx >> 4;
                    int seg = idx & 15;
                    const __half* src = sh + (long long)r * H_ + coff + seg * 8;
                    uint32_t dst = hsb + (uint32_t)kc * HC_BYTES
                                 + (uint32_t)(r * 136 + seg * 8) * 2;
                    CP_ASYNC16(dst, src);
                }
                CP_COMMIT();
            };
            auto consume = [&](int kc) {
                const uint32_t hb = hsb + (uint32_t)kc * HC_BYTES;
#pragma unroll
                for (int kk2 = 0; kk2 < 8; kk2++) {
                    uint32_t a[4], bf[4];
                    uint32_t ad = hb + (uint32_t)((mw * 16 + arow_l) * 136
                                                  + kk2 * 16 + acol_l) * 2;
                    LDSM_X4(a, ad);
                    int kg = kc * 8 + kk2;           // global k-tile 0..63
                    uint32_t bd = smb + (uint32_t)((nw * 16 + brow_l) * WS1_STR
                                                   + kg * 16 + bcol_l) * 2;
                    LDSM_X4(bf, bd);
                    mma_f16(acc[0], a, bf);
                    mma_f16(acc[1], a, bf + 2);
                }
            };

            if (t > 0) {
                // issue ALL 8 chunks upfront, then staggered waits
                issue(0); issue(1); issue(2); issue(3);
                issue(4); issue(5); issue(6); issue(7);
                CP_WAIT(7); __syncthreads(); consume(0);
                CP_WAIT(6); __syncthreads(); consume(1);
                CP_WAIT(5); __syncthreads(); consume(2);
                CP_WAIT(4); __syncthreads(); consume(3);
                CP_WAIT(3); __syncthreads(); consume(4);
                CP_WAIT(2); __syncthreads(); consume(5);
                CP_WAIT(1); __syncthreads(); consume(6);
                CP_WAIT(0); __syncthreads(); consume(7);
            } else {
                issue(0); issue(1); issue(2); issue(3);
                CP_WAIT(3); __syncthreads(); consume(0);
                CP_WAIT(2); __syncthreads(); consume(1);
                CP_WAIT(1); __syncthreads(); consume(2);
                CP_WAIT(0); __syncthreads(); consume(3);
            }

#pragma unroll
            for (int ni = 0; ni < 2; ni++) {
                int r = mw * 16 + (lane >> 2);
                int cb = nw * 16 + ni * 8 + (lane & 3) * 2;
                gs[r * 33 + cb]           = acc[ni][0];
                gs[r * 33 + cb + 1]       = acc[ni][1];
                gs[(r + 8) * 33 + cb]     = acc[ni][2];
                gs[(r + 8) * 33 + cb + 1] = acc[ni][3];
            }
            __syncthreads();

            const long long outoff = (long long)(t & 1) * B_ * H_;
#pragma unroll
            for (int i = 0; i < 2; i++) {
                int e = tx + i * 256;
                int b = e >> 3, u = e & 7;
                float gi = bs[0 * 8 + u] + gs[b * 33 + 0 * 8 + u];
                float gf = bs[1 * 8 + u] + gs[b * 33 + 1 * 8 + u];
                float gc = bs[2 * 8 + u] + gs[b * 33 + 2 * 8 + u];
                float go = bs[3 * 8 + u] + gs[b * 33 + 3 * 8 + u];
                float i_ = 1.f / (1.f + expf(-gi));
                float f_ = 1.f / (1.f + expf(-gf));
                float g_ = tanhf(gc);
                float o_ = 1.f / (1.f + expf(-go));
                float cold = (t == 0) ? 0.f : cs[e];
                float cn = f_ * cold + i_ * g_;
                cs[e] = cn;
                h1[outoff + (long long)b * H_ + j0 + u] = __float2half(o_ * tanhf(cn));
            }
        }

        // ---- grid barrier between stages ----
        if (s < T_) {
            __syncthreads();
            if (tx == 0) {
                unsigned target = (unsigned)(s + 1) * (unsigned)gridDim.x;
                asm volatile("red.release.gpu.global.add.u32 [%0], %1;"
                             :: "l"(bar), "r"(1u) : "memory");
                unsigned v;
                do {
                    asm volatile("ld.acquire.gpu.global.u32 %0, [%1];"
                                 : "=r"(v) : "l"(bar) : "memory");
                } while (v < target);
            }
            __syncthreads();
        }
    }
}

// ---------------------------------------------------------------------------
// Final FC on fp16 h
// ---------------------------------------------------------------------------
__global__ __launch_bounds__(128) void fc_kernel(
    const __half* __restrict__ h, const float* __restrict__ Wfc,
    const float* __restrict__ bfc, float* __restrict__ out)
{
    __shared__ float hrow[H_];
    int b = blockIdx.x;
    for (int k = threadIdx.x; k < H_; k += 128)
        hrow[k] = __half2float(h[b * H_ + k]);
    __syncthreads();

    int o = threadIdx.x;
    float s = bfc[o];
    const float4* w4 = reinterpret_cast<const float4*>(Wfc + (size_t)o * H_);
    const float4* h4 = reinterpret_cast<const float4*>(hrow);
#pragma unroll 4
    for (int k = 0; k < H_ / 4; k++) {
        float4 w = w4[k];
        float4 hh = h4[k];
        s += w.x * hh.x + w.y * hh.y + w.z * hh.z + w.w * hh.w;
    }
    out[b * OUT_ + o] = s;
}

// ---------------------------------------------------------------------------
extern "C" void kernel_launch(void* const* d_in, const int* in_sizes, int n_in,
                              void* d_out, int out_size)
{
    const float* x     = (const float*)d_in[0];
    const float* W_ih0 = (const float*)d_in[1];
    const float* W_hh0 = (const float*)d_in[2];
    const float* b_ih0 = (const float*)d_in[3];
    const float* b_hh0 = (const float*)d_in[4];
    const float* W_ih1 = (const float*)d_in[5];
    const float* W_hh1 = (const float*)d_in[6];
    const float* b_ih1 = (const float*)d_in[7];
    const float* b_hh1 = (const float*)d_in[8];
    const float* W_fc  = (const float*)d_in[9];
    const float* b_fc  = (const float*)d_in[10];
    float* out = (float*)d_out;

    float* xp;
    unsigned* bar;
    __nv_bfloat16 *xhi, *xlo, *whi, *wlo;
    __half *h0, *h1;
    cudaGetSymbolAddress((void**)&xp,  g_xp);
    cudaGetSymbolAddress((void**)&bar, g_bar);
    cudaGetSymbolAddress((void**)&xhi, g_Xhi);
    cudaGetSymbolAddress((void**)&xlo, g_Xlo);
    cudaGetSymbolAddress((void**)&whi, g_Whi);
    cudaGetSymbolAddress((void**)&wlo, g_Wlo);
    cudaGetSymbolAddress((void**)&h0,  g_h0);
    cudaGetSymbolAddress((void**)&h1,  g_h1);

    cudaFuncSetAttribute(gemm_mma_kernel,
                         cudaFuncAttributeMaxDynamicSharedMemorySize, GEMM_SMEM_BYTES);
    cudaFuncSetAttribute(lstm_fused_kernel,
                         cudaFuncAttributeMaxDynamicSharedMemorySize, FUSED_SMEM);

    dim3 mma_grid(G4_ / 128, M_ / 128);   // (16, 256)

    // layer-0 xp GEMM (K=128); first split also resets the grid barrier
    {
        int nA = M_ * IN_;
        int nW = G4_ * IN_;
        split_bf16_kernel<<<(nA + 255) / 256, 256>>>(x, xhi, xlo, nA, bar);
        split_bf16_kernel<<<(nW + 255) / 256, 256>>>(W_ih0, whi, wlo, nW, nullptr);
        gemm_mma_kernel<<<mma_grid, 256, GEMM_SMEM_BYTES>>>(xhi, xlo, whi, wlo,
                                                            b_ih0, b_hh0, xp, IN_);
    }

    // fused two-layer recurrence (pure fp16, lockstep barrier)
    lstm_fused_kernel<<<FBLK, RTHR, FUSED_SMEM>>>(
        xp, W_hh0, W_ih1, W_hh1, b_ih1, b_hh1, h0, h1, bar);

    // final FC on h1[t=511] (parity 1)
    fc_kernel<<<B_, 128>>>(h1 + (size_t)B_ * H_, W_fc, b_fc, out);
}

// round 13
// speedup vs baseline: 1.1961x; 1.0528x over previous
#include <cuda_runtime.h>
#include <cuda_bf16.h>
#include <cuda_fp16.h>
#include <math.h>
#include <stdint.h>

#define B_   64
#define T_   512
#define IN_  128
#define H_   512
#define G4_  2048   // 4*H
#define OUT_ 128
#define M_   (B_ * T_)   // 32768

#define FBLK 128    // fused grid: 64 layer-0 + 64 layer-1 blocks
#define RTHR 256
#define NGRP 8      // barrier groups (16 blocks each)

// ---------------- scratch (static device memory; no allocs) ----------------
__device__ float g_xp[(size_t)M_ * G4_];            // layer-0 gate preactivations
__device__ unsigned int g_bars[NGRP * 64];          // group counters, 256B apart

__device__ __nv_bfloat16 g_Xhi[(size_t)M_ * IN_];   // x split (front GEMM, bf16x3)
__device__ __nv_bfloat16 g_Xlo[(size_t)M_ * IN_];
__device__ __nv_bfloat16 g_Whi[(size_t)G4_ * IN_];  // W_ih0 split
__device__ __nv_bfloat16 g_Wlo[(size_t)G4_ * IN_];
__device__ __half g_h0[2 * B_ * H_];                // layer-0 h ping-pong (fp16)
__device__ __half g_h1[2 * B_ * H_];                // layer-1 h ping-pong (fp16)

// ======================= helpers ==============================
__device__ __forceinline__ uint32_t smem_u32(const void* p) {
    uint32_t a;
    asm("{ .reg .u64 t; cvta.to.shared.u64 t, %1; cvt.u32.u64 %0, t; }"
        : "=r"(a) : "l"(p));
    return a;
}

#define LDSM_X4(r, addr) \
    asm volatile("ldmatrix.sync.aligned.m8n8.x4.shared.b16 {%0,%1,%2,%3}, [%4];" \
        : "=r"((r)[0]), "=r"((r)[1]), "=r"((r)[2]), "=r"((r)[3]) : "r"(addr))
#define LDSM_X2(r, addr) \
    asm volatile("ldmatrix.sync.aligned.m8n8.x2.shared.b16 {%0,%1}, [%2];" \
        : "=r"((r)[0]), "=r"((r)[1]) : "r"(addr))

__device__ __forceinline__ void mma_bf16(float* d, const uint32_t* a, const uint32_t* b) {
    asm volatile("mma.sync.aligned.m16n8k16.row.col.f32.bf16.bf16.f32 "
        "{%0,%1,%2,%3}, {%4,%5,%6,%7}, {%8,%9}, {%0,%1,%2,%3};"
        : "+f"(d[0]), "+f"(d[1]), "+f"(d[2]), "+f"(d[3])
        : "r"(a[0]), "r"(a[1]), "r"(a[2]), "r"(a[3]), "r"(b[0]), "r"(b[1]));
}
__device__ __forceinline__ void mma_f16(float* d, const uint32_t* a, const uint32_t* b) {
    asm volatile("mma.sync.aligned.m16n8k16.row.col.f32.f16.f16.f32 "
        "{%0,%1,%2,%3}, {%4,%5,%6,%7}, {%8,%9}, {%0,%1,%2,%3};"
        : "+f"(d[0]), "+f"(d[1]), "+f"(d[2]), "+f"(d[3])
        : "r"(a[0]), "r"(a[1]), "r"(a[2]), "r"(a[3]), "r"(b[0]), "r"(b[1]));
}

#define CP_ASYNC16(dst, src) \
    asm volatile("cp.async.cg.shared.global [%0], [%1], 16;" :: "r"(dst), "l"(src))
#define CP_COMMIT() asm volatile("cp.async.commit_group;" ::: "memory")
#define CP_WAIT(n)  asm volatile("cp.async.wait_group %0;" :: "n"(n) : "memory")

__device__ __forceinline__ float sigmoid_fast(float x) {
    float e, r;
    asm("ex2.approx.f32 %0, %1;" : "=f"(e) : "f"(-1.4426950408889634f * x));
    asm("rcp.approx.f32 %0, %1;" : "=f"(r) : "f"(1.f + e));
    return r;
}
__device__ __forceinline__ float tanh_fast(float x) {
    float y;
    asm("tanh.approx.f32 %0, %1;" : "=f"(y) : "f"(x));
    return y;
}

// ---------------------------------------------------------------------------
// fp32 -> (hi, lo) bf16 split; optionally resets the group barrier counters
// ---------------------------------------------------------------------------
__global__ __launch_bounds__(256) void split_bf16_kernel(
    const float* __restrict__ in, __nv_bfloat16* __restrict__ hi,
    __nv_bfloat16* __restrict__ lo, int n, unsigned* bar_reset)
{
    if (bar_reset && blockIdx.x == 0 && threadIdx.x < NGRP)
        bar_reset[threadIdx.x * 64] = 0u;
    int i = blockIdx.x * 256 + threadIdx.x;
    if (i < n) {
        float v = in[i];
        __nv_bfloat16 h = __float2bfloat16(v);
        hi[i] = h;
        lo[i] = __float2bfloat16(v - __bfloat162float(h));
    }
}

// ---------------------------------------------------------------------------
// bf16x3 GEMM via mma.sync (layer-0 xp only; unchanged, passing since R3)
// ---------------------------------------------------------------------------
#define GSTRIDE 40
#define SMAT    (128 * GSTRIDE)
#define SSTAGE  (4 * SMAT)
#define GEMM_SMEM_BYTES (2 * SSTAGE * 2 + 128 * 4)

__global__ __launch_bounds__(256) void gemm_mma_kernel(
    const __nv_bfloat16* __restrict__ Ahi, const __nv_bfloat16* __restrict__ Alo,
    const __nv_bfloat16* __restrict__ Whi, const __nv_bfloat16* __restrict__ Wlo,
    const float* __restrict__ b1, const float* __restrict__ b2,
    float* __restrict__ C, int K)
{
    extern __shared__ __nv_bfloat16 sm[];
    float* biass = (float*)(sm + 2 * SSTAGE);

    const int tid  = threadIdx.x;
    const int wid  = tid >> 5;
    const int lane = tid & 31;
    const int wm   = wid >> 2;
    const int wn   = wid & 3;
    const int m0   = blockIdx.y * 128;
    const int n0   = blockIdx.x * 128;

    if (tid < 128) biass[tid] = b1[n0 + tid] + b2[n0 + tid];

    const int K8 = K >> 3;
    const uint4* gA[2] = { (const uint4*)Ahi, (const uint4*)Alo };
    const uint4* gW[2] = { (const uint4*)Whi, (const uint4*)Wlo };
    const uint32_t smb = smem_u32(sm);

    auto prefetch = [&](int kt, int st) {
        const int kk8 = kt * 4;
        const uint32_t sbase = smb + (uint32_t)st * (SSTAGE * 2);
#pragma unroll
        for (int hl = 0; hl < 2; hl++) {
#pragma unroll
            for (int i = 0; i < 2; i++) {
                int idx = tid + i * 256;
                int r = idx >> 2, j = idx & 3;
                uint32_t dst = sbase + (uint32_t)(hl * SMAT + r * GSTRIDE) * 2 + j * 16;
                CP_ASYNC16(dst, gA[hl] + (size_t)(m0 + r) * K8 + kk8 + j);
            }
#pragma unroll
            for (int i = 0; i < 2; i++) {
                int idx = tid + i * 256;
                int r = idx >> 2, j = idx & 3;
                uint32_t dst = sbase + (uint32_t)((2 + hl) * SMAT + r * GSTRIDE) * 2 + j * 16;
                CP_ASYNC16(dst, gW[hl] + (size_t)(n0 + r) * K8 + kk8 + j);
            }
        }
        CP_COMMIT();
    };

    float acc[4][4][4];
#pragma unroll
    for (int mi = 0; mi < 4; mi++)
#pragma unroll
        for (int ni = 0; ni < 4; ni++)
#pragma unroll
            for (int e = 0; e < 4; e++) acc[mi][ni][e] = 0.f;

    const int KT = K / 32;
    prefetch(0, 0);

    for (int kt = 0; kt < KT; kt++) {
        if (kt + 1 < KT) { prefetch(kt + 1, (kt + 1) & 1); CP_WAIT(1); }
        else             { CP_WAIT(0); }
        __syncthreads();

        const uint32_t sbase = smb + (uint32_t)(kt & 1) * (SSTAGE * 2);
#pragma unroll
        for (int ks = 0; ks < 2; ks++) {
            uint32_t aH[4][4], aL[4][4], bH[4][2], bL[4][2];

            const int arow = wm * 64 + (lane & 7) + ((lane >> 3) & 1) * 8;
            const int acol = ks * 16 + (lane >> 4) * 8;
#pragma unroll
            for (int mi = 0; mi < 4; mi++) {
                uint32_t ad = sbase + (uint32_t)((arow + mi * 16) * GSTRIDE + acol) * 2;
                LDSM_X4(aH[mi], ad);
                LDSM_X4(aL[mi], ad + SMAT * 2);
            }
            const int l16  = lane & 15;
            const int brow = wn * 32 + (l16 & 7);
            const int bcol = ks * 16 + (l16 >> 3) * 8;
#pragma unroll
            for (int ni = 0; ni < 4; ni++) {
                uint32_t bd = sbase + (uint32_t)(2 * SMAT + (brow + ni * 8) * GSTRIDE + bcol) * 2;
                LDSM_X2(bH[ni], bd);
                LDSM_X2(bL[ni], bd + SMAT * 2);
            }
#pragma unroll
            for (int mi = 0; mi < 4; mi++)
#pragma unroll
                for (int ni = 0; ni < 4; ni++) {
                    mma_bf16(acc[mi][ni], aH[mi], bH[ni]);
                    mma_bf16(acc[mi][ni], aH[mi], bL[ni]);
                    mma_bf16(acc[mi][ni], aL[mi], bH[ni]);
                }
        }
        __syncthreads();
    }

#pragma unroll
    for (int mi = 0; mi < 4; mi++) {
        const int r0 = m0 + wm * 64 + mi * 16 + (lane >> 2);
#pragma unroll
        for (int ni = 0; ni < 4; ni++) {
            const int c = wn * 32 + ni * 8 + (lane & 3) * 2;
            float2 v0, v1;
            v0.x = acc[mi][ni][0] + biass[c];
            v0.y = acc[mi][ni][1] + biass[c + 1];
            v1.x = acc[mi][ni][2] + biass[c];
            v1.y = acc[mi][ni][3] + biass[c + 1];
            *(float2*)&C[(size_t)r0 * G4_ + n0 + c]       = v0;
            *(float2*)&C[(size_t)(r0 + 8) * G4_ + n0 + c] = v1;
        }
    }
}

// ---------------------------------------------------------------------------
// FUSED two-layer persistent LSTM, pure fp16, lockstep TWO-LEVEL barrier.
// Barrier: 8 group counters 256B apart; red.release.add per block; lanes 0-7
// poll all 8 counters in parallel until every group hits (s+1)*16.
// Cell epilogue uses MUFU approx sigmoid/tanh.
// ---------------------------------------------------------------------------
// layer-0 SMEM layout
#define WS0_STR   520
#define HS0_OFF   33280u            // 32*520*2
#define HC_BYTES  17408u            // 64*136*2 per 128-col chunk
#define XS0_OFF   102912u           // HS0_OFF + 4*HC_BYTES
#define GS0_OFF   111104u
#define CS0_OFF   119552u
// layer-1 SMEM layout
#define WS1_STR   1048
#define HS1_OFF   67072u            // 8 chunk slots (h0: 0..3, h1: 4..7)
#define GS1_OFF   206336u           // HS1_OFF + 8*HC_BYTES
#define CS1_OFF   214784u
#define BS1_OFF   216832u
#define FUSED_SMEM 217088

__global__ __launch_bounds__(RTHR, 1) void lstm_fused_kernel(
    const float* __restrict__ xp0, const float* __restrict__ Whh0,
    const float* __restrict__ Wih1, const float* __restrict__ Whh1,
    const float* __restrict__ b_ih1, const float* __restrict__ b_hh1,
    __half* __restrict__ h0, __half* __restrict__ h1,
    unsigned* __restrict__ bars)
{
    extern __shared__ char sm8[];
    const int tx   = threadIdx.x;
    const int wid  = tx >> 5;
    const int lane = tx & 31;
    const int mw   = wid >> 1;           // 0..3  (M16 of 64 batch rows)
    const int nw   = wid & 1;            // 0..1  (N16 of 32 gate cols)
    const bool isL0 = blockIdx.x < 64;
    const int j0   = (blockIdx.x & 63) * 8;
    const int grp  = blockIdx.x >> 4;    // 0..7 (16 blocks per group)

    const uint32_t smb = smem_u32(sm8);
    __half* ws = (__half*)sm8;

    // fragment addressing helpers
    const int arow_l = (lane & 7) + ((lane >> 3) & 1) * 8;   // + mw*16
    const int acol_l = (lane >> 4) * 8;
    const int brow_l = ((lane >> 4) & 1) * 8 + (lane & 7);   // + nw*16
    const int bcol_l = ((lane >> 3) & 1) * 8;

    if (isL0) {
        // ---- layer-0 setup: W_hh0 slice -> fp16 (stride 520) ----
#pragma unroll 4
        for (int i = 0; i < 64; i++) {
            int idx = tx + i * 256;
            int cc = idx >> 9, k = idx & 511;
            int gg = cc >> 3, u = cc & 7;
            ws[cc * WS0_STR + k] =
                __float2half(Whh0[(size_t)(gg * H_ + j0 + u) * H_ + k]);
        }
    } else {
        // ---- layer-1 setup: [W_ih1 ; W_hh1] slice -> fp16 (stride 1048) ----
#pragma unroll 4
        for (int i = 0; i < 128; i++) {
            int idx = tx + i * 256;
            int cc = idx >> 10, k = idx & 1023;
            int gg = cc >> 3, u = cc & 7;
            size_t row = (size_t)(gg * H_ + j0 + u) * H_;
            float w = (k < 512) ? Wih1[row + k] : Whh1[row + k - 512];
            ws[cc * WS1_STR + k] = __float2half(w);
        }
        if (tx < 32) {
            int gg = tx >> 3, u = tx & 7;
            ((float*)(sm8 + BS1_OFF))[tx] =
                b_ih1[gg * H_ + j0 + u] + b_hh1[gg * H_ + j0 + u];
        }
    }
    __syncthreads();

    float acc[2][4];

    for (int s = 0; s <= T_; s++) {
        if (isL0 && s < T_) {
            // ================= layer-0 step s =================
            const int t = s;
            float* xs = (float*)(sm8 + XS0_OFF);
            float* gs = (float*)(sm8 + GS0_OFF);
            float* cs = (float*)(sm8 + CS0_OFF);
            const uint32_t hsb = smb + HS0_OFF;

            // group 0: xp tile
#pragma unroll
            for (int i = 0; i < 2; i++) {
                int idx = tx + i * 256;
                int b = idx >> 3, gg = (idx >> 1) & 3, seg = idx & 1;
                uint32_t dst = smb + XS0_OFF + (uint32_t)(b * 32 + gg * 8 + seg * 4) * 4;
                CP_ASYNC16(dst, xp0 + ((size_t)b * T_ + t) * G4_ + gg * H_ + j0 + seg * 4);
            }
            CP_COMMIT();

#pragma unroll
            for (int ni = 0; ni < 2; ni++)
#pragma unroll
                for (int e = 0; e < 4; e++) acc[ni][e] = 0.f;

            if (t > 0) {
                const long long inoff = (long long)((t & 1) ^ 1) * B_ * H_;
                // groups 1..4: four 128-col chunks of h0 (fp16)
#pragma unroll
                for (int c = 0; c < 4; c++) {
#pragma unroll
                    for (int i = 0; i < 4; i++) {
                        int idx = tx + i * 256;
                        int r   = idx >> 4;
                        int seg = idx & 15;
                        const __half* src = h0 + inoff + (long long)r * H_ + c * 128 + seg * 8;
                        uint32_t dst = hsb + (uint32_t)c * HC_BYTES
                                     + (uint32_t)(r * 136 + seg * 8) * 2;
                        CP_ASYNC16(dst, src);
                    }
                    CP_COMMIT();
                }

                auto consume = [&](int c) {
                    const uint32_t hb = hsb + (uint32_t)c * HC_BYTES;
#pragma unroll
                    for (int kk2 = 0; kk2 < 8; kk2++) {
                        uint32_t a[4], bf[4];
                        uint32_t ad = hb + (uint32_t)((mw * 16 + arow_l) * 136
                                                      + kk2 * 16 + acol_l) * 2;
                        LDSM_X4(a, ad);
                        int kg = c * 8 + kk2;
                        uint32_t bd = smb + (uint32_t)((nw * 16 + brow_l) * WS0_STR
                                                       + kg * 16 + bcol_l) * 2;
                        LDSM_X4(bf, bd);
                        mma_f16(acc[0], a, bf);
                        mma_f16(acc[1], a, bf + 2);
                    }
                };
                CP_WAIT(3); __syncthreads(); consume(0);
                CP_WAIT(2); __syncthreads(); consume(1);
                CP_WAIT(1); __syncthreads(); consume(2);
                CP_WAIT(0); __syncthreads(); consume(3);

#pragma unroll
                for (int ni = 0; ni < 2; ni++) {
                    int r = mw * 16 + (lane >> 2);
                    int cb = nw * 16 + ni * 8 + (lane & 3) * 2;
                    gs[r * 33 + cb]           = acc[ni][0];
                    gs[r * 33 + cb + 1]       = acc[ni][1];
                    gs[(r + 8) * 33 + cb]     = acc[ni][2];
                    gs[(r + 8) * 33 + cb + 1] = acc[ni][3];
                }
            } else {
                CP_WAIT(0);
            }
            __syncthreads();

            const long long outoff = (long long)(t & 1) * B_ * H_;
#pragma unroll
            for (int i = 0; i < 2; i++) {
                int e = tx + i * 256;
                int b = e >> 3, u = e & 7;
                float gi = xs[b * 32 + 0 * 8 + u];
                float gf = xs[b * 32 + 1 * 8 + u];
                float gc = xs[b * 32 + 2 * 8 + u];
                float go = xs[b * 32 + 3 * 8 + u];
                if (t > 0) {
                    gi += gs[b * 33 + 0 * 8 + u];
                    gf += gs[b * 33 + 1 * 8 + u];
                    gc += gs[b * 33 + 2 * 8 + u];
                    go += gs[b * 33 + 3 * 8 + u];
                }
                float i_ = sigmoid_fast(gi);
                float f_ = sigmoid_fast(gf);
                float g_ = tanh_fast(gc);
                float o_ = sigmoid_fast(go);
                float cold = (t == 0) ? 0.f : cs[e];
                float cn = f_ * cold + i_ * g_;
                cs[e] = cn;
                h0[outoff + (long long)b * H_ + j0 + u] = __float2half(o_ * tanh_fast(cn));
            }
        } else if (!isL0 && s >= 1) {
            // ================= layer-1 step t = s-1 =================
            const int t = s - 1;
            float* gs = (float*)(sm8 + GS1_OFF);
            float* cs = (float*)(sm8 + CS1_OFF);
            float* bs = (float*)(sm8 + BS1_OFF);
            const uint32_t hsb = smb + HS1_OFF;

#pragma unroll
            for (int ni = 0; ni < 2; ni++)
#pragma unroll
                for (int e = 0; e < 4; e++) acc[ni][e] = 0.f;

            const long long in0 = (long long)(t & 1) * B_ * H_;         // h0[t]
            const long long in1 = (long long)((t & 1) ^ 1) * B_ * H_;   // h1[t-1]

            auto issue = [&](int kc) {
                const __half* sh;
                int coff;
                if (kc < 4) { sh = h0 + in0; coff = kc * 128; }
                else        { sh = h1 + in1; coff = (kc - 4) * 128; }
#pragma unroll
                for (int i = 0; i < 4; i++) {
                    int idx = tx + i * 256;
                    int r   = idx >> 4;
                    int seg = idx & 15;
                    const __half* src = sh + (long long)r * H_ + coff + seg * 8;
                    uint32_t dst = hsb + (uint32_t)kc * HC_BYTES
                                 + (uint32_t)(r * 136 + seg * 8) * 2;
                    CP_ASYNC16(dst, src);
                }
                CP_COMMIT();
            };
            auto consume = [&](int kc) {
                const uint32_t hb = hsb + (uint32_t)kc * HC_BYTES;
#pragma unroll
                for (int kk2 = 0; kk2 < 8; kk2++) {
                    uint32_t a[4], bf[4];
                    uint32_t ad = hb + (uint32_t)((mw * 16 + arow_l) * 136
                                                  + kk2 * 16 + acol_l) * 2;
                    LDSM_X4(a, ad);
                    int kg = kc * 8 + kk2;           // global k-tile 0..63
                    uint32_t bd = smb + (uint32_t)((nw * 16 + brow_l) * WS1_STR
                                                   + kg * 16 + bcol_l) * 2;
                    LDSM_X4(bf, bd);
                    mma_f16(acc[0], a, bf);
                    mma_f16(acc[1], a, bf + 2);
                }
            };

            if (t > 0) {
                issue(0); issue(1); issue(2); issue(3);
                issue(4); issue(5); issue(6); issue(7);
                CP_WAIT(7); __syncthreads(); consume(0);
                CP_WAIT(6); __syncthreads(); consume(1);
                CP_WAIT(5); __syncthreads(); consume(2);
                CP_WAIT(4); __syncthreads(); consume(3);
                CP_WAIT(3); __syncthreads(); consume(4);
                CP_WAIT(2); __syncthreads(); consume(5);
                CP_WAIT(1); __syncthreads(); consume(6);
                CP_WAIT(0); __syncthreads(); consume(7);
            } else {
                issue(0); issue(1); issue(2); issue(3);
                CP_WAIT(3); __syncthreads(); consume(0);
                CP_WAIT(2); __syncthreads(); consume(1);
                CP_WAIT(1); __syncthreads(); consume(2);
                CP_WAIT(0); __syncthreads(); consume(3);
            }

#pragma unroll
            for (int ni = 0; ni < 2; ni++) {
                int r = mw * 16 + (lane >> 2);
                int cb = nw * 16 + ni * 8 + (lane & 3) * 2;
                gs[r * 33 + cb]           = acc[ni][0];
                gs[r * 33 + cb + 1]       = acc[ni][1];
                gs[(r + 8) * 33 + cb]     = acc[ni][2];
                gs[(r + 8) * 33 + cb + 1] = acc[ni][3];
            }
            __syncthreads();

            const long long outoff = (long long)(t & 1) * B_ * H_;
#pragma unroll
            for (int i = 0; i < 2; i++) {
                int e = tx + i * 256;
                int b = e >> 3, u = e & 7;
                float gi = bs[0 * 8 + u] + gs[b * 33 + 0 * 8 + u];
                float gf = bs[1 * 8 + u] + gs[b * 33 + 1 * 8 + u];
                float gc = bs[2 * 8 + u] + gs[b * 33 + 2 * 8 + u];
                float go = bs[3 * 8 + u] + gs[b * 33 + 3 * 8 + u];
                float i_ = sigmoid_fast(gi);
                float f_ = sigmoid_fast(gf);
                float g_ = tanh_fast(gc);
                float o_ = sigmoid_fast(go);
                float cold = (t == 0) ? 0.f : cs[e];
                float cn = f_ * cold + i_ * g_;
                cs[e] = cn;
                h1[outoff + (long long)b * H_ + j0 + u] = __float2half(o_ * tanh_fast(cn));
            }
        }

        // ---- two-level grid barrier between stages ----
        if (s < T_) {
            __syncthreads();
            if (tx == 0) {
                asm volatile("red.release.gpu.global.add.u32 [%0], %1;"
                             :: "l"(bars + grp * 64), "r"(1u) : "memory");
            }
            if (tx < NGRP) {
                unsigned target = (unsigned)(s + 1) * 16u;
                unsigned* p = bars + tx * 64;
                unsigned v;
                do {
                    asm volatile("ld.acquire.gpu.global.u32 %0, [%1];"
                                 : "=r"(v) : "l"(p) : "memory");
                } while (v < target);
            }
            __syncthreads();
        }
    }
}

// ---------------------------------------------------------------------------
// Final FC on fp16 h
// ---------------------------------------------------------------------------
__global__ __launch_bounds__(128) void fc_kernel(
    const __half* __restrict__ h, const float* __restrict__ Wfc,
    const float* __restrict__ bfc, float* __restrict__ out)
{
    __shared__ float hrow[H_];
    int b = blockIdx.x;
    for (int k = threadIdx.x; k < H_; k += 128)
        hrow[k] = __half2float(h[b * H_ + k]);
    __syncthreads();

    int o = threadIdx.x;
    float s = bfc[o];
    const float4* w4 = reinterpret_cast<const float4*>(Wfc + (size_t)o * H_);
    const float4* h4 = reinterpret_cast<const float4*>(hrow);
#pragma unroll 4
    for (int k = 0; k < H_ / 4; k++) {
        float4 w = w4[k];
        float4 hh = h4[k];
        s += w.x * hh.x + w.y * hh.y + w.z * hh.z + w.w * hh.w;
    }
    out[b * OUT_ + o] = s;
}

// ---------------------------------------------------------------------------
extern "C" void kernel_launch(void* const* d_in, const int* in_sizes, int n_in,
                              void* d_out, int out_size)
{
    const float* x     = (const float*)d_in[0];
    const float* W_ih0 = (const float*)d_in[1];
    const float* W_hh0 = (const float*)d_in[2];
    const float* b_ih0 = (const float*)d_in[3];
    const float* b_hh0 = (const float*)d_in[4];
    const float* W_ih1 = (const float*)d_in[5];
    const float* W_hh1 = (const float*)d_in[6];
    const float* b_ih1 = (const float*)d_in[7];
    const float* b_hh1 = (const float*)d_in[8];
    const float* W_fc  = (const float*)d_in[9];
    const float* b_fc  = (const float*)d_in[10];
    float* out = (float*)d_out;

    float* xp;
    unsigned* bars;
    __nv_bfloat16 *xhi, *xlo, *whi, *wlo;
    __half *h0, *h1;
    cudaGetSymbolAddress((void**)&xp,   g_xp);
    cudaGetSymbolAddress((void**)&bars, g_bars);
    cudaGetSymbolAddress((void**)&xhi,  g_Xhi);
    cudaGetSymbolAddress((void**)&xlo,  g_Xlo);
    cudaGetSymbolAddress((void**)&whi,  g_Whi);
    cudaGetSymbolAddress((void**)&wlo,  g_Wlo);
    cudaGetSymbolAddress((void**)&h0,   g_h0);
    cudaGetSymbolAddress((void**)&h1,   g_h1);

    cudaFuncSetAttribute(gemm_mma_kernel,
                         cudaFuncAttributeMaxDynamicSharedMemorySize, GEMM_SMEM_BYTES);
    cudaFuncSetAttribute(lstm_fused_kernel,
                         cudaFuncAttributeMaxDynamicSharedMemorySize, FUSED_SMEM);

    dim3 mma_grid(G4_ / 128, M_ / 128);   // (16, 256)

    // layer-0 xp GEMM (K=128); first split also resets the barrier counters
    {
        int nA = M_ * IN_;
        int nW = G4_ * IN_;
        split_bf16_kernel<<<(nA + 255) / 256, 256>>>(x, xhi, xlo, nA, bars);
        split_bf16_kernel<<<(nW + 255) / 256, 256>>>(W_ih0, whi, wlo, nW, nullptr);
        gemm_mma_kernel<<<mma_grid, 256, GEMM_SMEM_BYTES>>>(xhi, xlo, whi, wlo,
                                                            b_ih0, b_hh0, xp, IN_);
    }

    // fused two-layer recurrence (pure fp16, two-level lockstep barrier)
    lstm_fused_kernel<<<FBLK, RTHR, FUSED_SMEM>>>(
        xp, W_hh0, W_ih1, W_hh1, b_ih1, b_hh1, h0, h1, bars);

    // final FC on h1[t=511] (parity 1)
    fc_kernel<<<B_, 128>>>(h1 + (size_t)B_ * H_, W_fc, b_fc, out);
}

// round 14
// speedup vs baseline: 1.3956x; 1.1668x over previous
#include <cuda_runtime.h>
#include <cuda_bf16.h>
#include <cuda_fp16.h>
#include <math.h>
#include <stdint.h>

#define B_   64
#define T_   512
#define IN_  128
#define H_   512
#define G4_  2048   // 4*H
#define OUT_ 128
#define M_   (B_ * T_)   // 32768

#define FBLK 128    // fused grid: 64 layer-0 + 64 layer-1 blocks
#define FTHR 128    // 4 warps per block (warp = 16 batch rows x 32 gate cols)
#define NGRP 8      // barrier groups (16 blocks each)

// ---------------- scratch (static device memory; no allocs) ----------------
__device__ float g_xp[(size_t)M_ * G4_];            // layer-0 gate preactivations
__device__ unsigned int g_bars[NGRP * 64];          // group counters, 256B apart

__device__ __nv_bfloat16 g_Xhi[(size_t)M_ * IN_];   // x split (front GEMM, bf16x3)
__device__ __nv_bfloat16 g_Xlo[(size_t)M_ * IN_];
__device__ __nv_bfloat16 g_Whi[(size_t)G4_ * IN_];  // W_ih0 split
__device__ __nv_bfloat16 g_Wlo[(size_t)G4_ * IN_];
__device__ __half g_h0[2 * B_ * H_];                // layer-0 h ping-pong (fp16)
__device__ __half g_h1[2 * B_ * H_];                // layer-1 h ping-pong (fp16)

// ======================= helpers ==============================
__device__ __forceinline__ uint32_t smem_u32(const void* p) {
    uint32_t a;
    asm("{ .reg .u64 t; cvta.to.shared.u64 t, %1; cvt.u32.u64 %0, t; }"
        : "=r"(a) : "l"(p));
    return a;
}

#define LDSM_X4(r, addr) \
    asm volatile("ldmatrix.sync.aligned.m8n8.x4.shared.b16 {%0,%1,%2,%3}, [%4];" \
        : "=r"((r)[0]), "=r"((r)[1]), "=r"((r)[2]), "=r"((r)[3]) : "r"(addr))
#define LDSM_X2(r, addr) \
    asm volatile("ldmatrix.sync.aligned.m8n8.x2.shared.b16 {%0,%1}, [%2];" \
        : "=r"((r)[0]), "=r"((r)[1]) : "r"(addr))

__device__ __forceinline__ void mma_bf16(float* d, const uint32_t* a, const uint32_t* b) {
    asm volatile("mma.sync.aligned.m16n8k16.row.col.f32.bf16.bf16.f32 "
        "{%0,%1,%2,%3}, {%4,%5,%6,%7}, {%8,%9}, {%0,%1,%2,%3};"
        : "+f"(d[0]), "+f"(d[1]), "+f"(d[2]), "+f"(d[3])
        : "r"(a[0]), "r"(a[1]), "r"(a[2]), "r"(a[3]), "r"(b[0]), "r"(b[1]));
}
__device__ __forceinline__ void mma_f16(float* d, const uint32_t* a, const uint32_t* b) {
    asm volatile("mma.sync.aligned.m16n8k16.row.col.f32.f16.f16.f32 "
        "{%0,%1,%2,%3}, {%4,%5,%6,%7}, {%8,%9}, {%0,%1,%2,%3};"
        : "+f"(d[0]), "+f"(d[1]), "+f"(d[2]), "+f"(d[3])
        : "r"(a[0]), "r"(a[1]), "r"(a[2]), "r"(a[3]), "r"(b[0]), "r"(b[1]));
}

#define CP_ASYNC16(dst, src) \
    asm volatile("cp.async.cg.shared.global [%0], [%1], 16;" :: "r"(dst), "l"(src))
#define CP_COMMIT() asm volatile("cp.async.commit_group;" ::: "memory")
#define CP_WAIT(n)  asm volatile("cp.async.wait_group %0;" :: "n"(n) : "memory")

__device__ __forceinline__ float sigmoid_fast(float x) {
    float e, r;
    asm("ex2.approx.f32 %0, %1;" : "=f"(e) : "f"(-1.4426950408889634f * x));
    asm("rcp.approx.f32 %0, %1;" : "=f"(r) : "f"(1.f + e));
    return r;
}
__device__ __forceinline__ float tanh_fast(float x) {
    float y;
    asm("tanh.approx.f32 %0, %1;" : "=f"(y) : "f"(x));
    return y;
}

// ---------------------------------------------------------------------------
// fp32 -> (hi, lo) bf16 split; optionally resets the group barrier counters
// ---------------------------------------------------------------------------
__global__ __launch_bounds__(256) void split_bf16_kernel(
    const float* __restrict__ in, __nv_bfloat16* __restrict__ hi,
    __nv_bfloat16* __restrict__ lo, int n, unsigned* bar_reset)
{
    if (bar_reset && blockIdx.x == 0 && threadIdx.x < NGRP)
        bar_reset[threadIdx.x * 64] = 0u;
    int i = blockIdx.x * 256 + threadIdx.x;
    if (i < n) {
        float v = in[i];
        __nv_bfloat16 h = __float2bfloat16(v);
        hi[i] = h;
        lo[i] = __float2bfloat16(v - __bfloat162float(h));
    }
}

// ---------------------------------------------------------------------------
// bf16x3 GEMM via mma.sync (layer-0 xp only; unchanged, passing since R3)
// ---------------------------------------------------------------------------
#define GSTRIDE 40
#define SMAT    (128 * GSTRIDE)
#define SSTAGE  (4 * SMAT)
#define GEMM_SMEM_BYTES (2 * SSTAGE * 2 + 128 * 4)

__global__ __launch_bounds__(256) void gemm_mma_kernel(
    const __nv_bfloat16* __restrict__ Ahi, const __nv_bfloat16* __restrict__ Alo,
    const __nv_bfloat16* __restrict__ Whi, const __nv_bfloat16* __restrict__ Wlo,
    const float* __restrict__ b1, const float* __restrict__ b2,
    float* __restrict__ C, int K)
{
    extern __shared__ __nv_bfloat16 sm[];
    float* biass = (float*)(sm + 2 * SSTAGE);

    const int tid  = threadIdx.x;
    const int wid  = tid >> 5;
    const int lane = tid & 31;
    const int wm   = wid >> 2;
    const int wn   = wid & 3;
    const int m0   = blockIdx.y * 128;
    const int n0   = blockIdx.x * 128;

    if (tid < 128) biass[tid] = b1[n0 + tid] + b2[n0 + tid];

    const int K8 = K >> 3;
    const uint4* gA[2] = { (const uint4*)Ahi, (const uint4*)Alo };
    const uint4* gW[2] = { (const uint4*)Whi, (const uint4*)Wlo };
    const uint32_t smb = smem_u32(sm);

    auto prefetch = [&](int kt, int st) {
        const int kk8 = kt * 4;
        const uint32_t sbase = smb + (uint32_t)st * (SSTAGE * 2);
#pragma unroll
        for (int hl = 0; hl < 2; hl++) {
#pragma unroll
            for (int i = 0; i < 2; i++) {
                int idx = tid + i * 256;
                int r = idx >> 2, j = idx & 3;
                uint32_t dst = sbase + (uint32_t)(hl * SMAT + r * GSTRIDE) * 2 + j * 16;
                CP_ASYNC16(dst, gA[hl] + (size_t)(m0 + r) * K8 + kk8 + j);
            }
#pragma unroll
            for (int i = 0; i < 2; i++) {
                int idx = tid + i * 256;
                int r = idx >> 2, j = idx & 3;
                uint32_t dst = sbase + (uint32_t)((2 + hl) * SMAT + r * GSTRIDE) * 2 + j * 16;
                CP_ASYNC16(dst, gW[hl] + (size_t)(n0 + r) * K8 + kk8 + j);
            }
        }
        CP_COMMIT();
    };

    float acc[4][4][4];
#pragma unroll
    for (int mi = 0; mi < 4; mi++)
#pragma unroll
        for (int ni = 0; ni < 4; ni++)
#pragma unroll
            for (int e = 0; e < 4; e++) acc[mi][ni][e] = 0.f;

    const int KT = K / 32;
    prefetch(0, 0);

    for (int kt = 0; kt < KT; kt++) {
        if (kt + 1 < KT) { prefetch(kt + 1, (kt + 1) & 1); CP_WAIT(1); }
        else             { CP_WAIT(0); }
        __syncthreads();

        const uint32_t sbase = smb + (uint32_t)(kt & 1) * (SSTAGE * 2);
#pragma unroll
        for (int ks = 0; ks < 2; ks++) {
            uint32_t aH[4][4], aL[4][4], bH[4][2], bL[4][2];

            const int arow = wm * 64 + (lane & 7) + ((lane >> 3) & 1) * 8;
            const int acol = ks * 16 + (lane >> 4) * 8;
#pragma unroll
            for (int mi = 0; mi < 4; mi++) {
                uint32_t ad = sbase + (uint32_t)((arow + mi * 16) * GSTRIDE + acol) * 2;
                LDSM_X4(aH[mi], ad);
                LDSM_X4(aL[mi], ad + SMAT * 2);
            }
            const int l16  = lane & 15;
            const int brow = wn * 32 + (l16 & 7);
            const int bcol = ks * 16 + (l16 >> 3) * 8;
#pragma unroll
            for (int ni = 0; ni < 4; ni++) {
                uint32_t bd = sbase + (uint32_t)(2 * SMAT + (brow + ni * 8) * GSTRIDE + bcol) * 2;
                LDSM_X2(bH[ni], bd);
                LDSM_X2(bL[ni], bd + SMAT * 2);
            }
#pragma unroll
            for (int mi = 0; mi < 4; mi++)
#pragma unroll
                for (int ni = 0; ni < 4; ni++) {
                    mma_bf16(acc[mi][ni], aH[mi], bH[ni]);
                    mma_bf16(acc[mi][ni], aH[mi], bL[ni]);
                    mma_bf16(acc[mi][ni], aL[mi], bH[ni]);
                }
        }
        __syncthreads();
    }

#pragma unroll
    for (int mi = 0; mi < 4; mi++) {
        const int r0 = m0 + wm * 64 + mi * 16 + (lane >> 2);
#pragma unroll
        for (int ni = 0; ni < 4; ni++) {
            const int c = wn * 32 + ni * 8 + (lane & 3) * 2;
            float2 v0, v1;
            v0.x = acc[mi][ni][0] + biass[c];
            v0.y = acc[mi][ni][1] + biass[c + 1];
            v1.x = acc[mi][ni][2] + biass[c];
            v1.y = acc[mi][ni][3] + biass[c + 1];
            *(float2*)&C[(size_t)r0 * G4_ + n0 + c]       = v0;
            *(float2*)&C[(size_t)(r0 + 8) * G4_ + n0 + c] = v1;
        }
    }
}

// ---------------------------------------------------------------------------
// FUSED two-layer persistent LSTM — WARP-SYNCHRONOUS steps.
// 128 blocks x 128 threads (4 warps). Warp mw owns 16 batch rows x all 32
// gate cols. Each warp cp.asyncs its own h rows (private SMEM), waits with
// cp.async.wait_group + __syncwarp (no block syncs in the matmul), and the
// D-fragment layout gives each thread all 4 gates of its units -> cell update
// and c-state entirely in registers. Only the inter-block barrier syncs.
// ---------------------------------------------------------------------------
// layer-0: W 32x520 fp16 (33280 B); staging per warp 4 chunks x 16x136 fp16
#define WS0_STR   520
#define HS0_OFF   33280u
#define HCW_BYTES 4352u             // 16*136*2 per chunk per warp
#define W0_STAGE  17408u            // 4 chunks per warp
// layer-1: W 32x1048 fp16 (67072 B); staging per warp 8 chunks
#define WS1_STR   1048
#define HS1_OFF   67072u
#define W1_STAGE  34816u            // 8 chunks per warp
#define FUSED_SMEM 206336           // HS1_OFF + 4*W1_STAGE

__global__ __launch_bounds__(FTHR, 1) void lstm_fused_kernel(
    const float* __restrict__ xp0, const float* __restrict__ Whh0,
    const float* __restrict__ Wih1, const float* __restrict__ Whh1,
    const float* __restrict__ b_ih1, const float* __restrict__ b_hh1,
    __half* __restrict__ h0, __half* __restrict__ h1,
    unsigned* __restrict__ bars)
{
    extern __shared__ char sm8[];
    const int tx   = threadIdx.x;
    const int wid  = tx >> 5;            // warp = mw, 0..3
    const int lane = tx & 31;
    const bool isL0 = blockIdx.x < 64;
    const int j0   = (blockIdx.x & 63) * 8;
    const int grp  = blockIdx.x >> 4;

    const uint32_t smb = smem_u32(sm8);
    __half* ws = (__half*)sm8;

    // fragment addressing
    const int arow_l = (lane & 7) + ((lane >> 3) & 1) * 8;
    const int acol_l = (lane >> 4) * 8;
    const int brow_l = ((lane >> 4) & 1) * 8 + (lane & 7);
    const int bcol_l = ((lane >> 3) & 1) * 8;

    // cell-ownership mapping (m16n8k16 D fragment)
    const int r0 = lane >> 2;            // rows r0, r0+8 (within warp's 16)
    const int u0 = (lane & 3) * 2;       // units u0, u0+1

    float bias_v[4][2];                  // L1 bias per gate for (u0,u1)

    if (isL0) {
        // W_hh0 slice -> fp16 (stride 520), cc = gg*8+u
        for (int i = 0; i < 128; i++) {
            int idx = tx + i * 128;
            int cc = idx >> 9, k = idx & 511;
            int gg = cc >> 3, u = cc & 7;
            ws[cc * WS0_STR + k] =
                __float2half(Whh0[(size_t)(gg * H_ + j0 + u) * H_ + k]);
        }
    } else {
        // [W_ih1 ; W_hh1] slice -> fp16 (stride 1048)
        for (int i = 0; i < 256; i++) {
            int idx = tx + i * 128;
            int cc = idx >> 10, k = idx & 1023;
            int gg = cc >> 3, u = cc & 7;
            size_t row = (size_t)(gg * H_ + j0 + u) * H_;
            float w = (k < 512) ? Wih1[row + k] : Whh1[row + k - 512];
            ws[cc * WS1_STR + k] = __float2half(w);
        }
#pragma unroll
        for (int g = 0; g < 4; g++) {
            bias_v[g][0] = b_ih1[g * H_ + j0 + u0]     + b_hh1[g * H_ + j0 + u0];
            bias_v[g][1] = b_ih1[g * H_ + j0 + u0 + 1] + b_hh1[g * H_ + j0 + u0 + 1];
        }
    }
    __syncthreads();

    float acc[4][4];     // acc[gate][e]
    float cst[4];        // cell state in registers, e-indexed
#pragma unroll
    for (int e = 0; e < 4; e++) cst[e] = 0.f;

    const uint32_t hsb = smb + (isL0 ? HS0_OFF : HS1_OFF)
                       + (uint32_t)wid * (isL0 ? W0_STAGE : W1_STAGE);
    const int wrow0 = wid * 16;          // warp's first batch row

    for (int s = 0; s <= T_; s++) {
        if (isL0 && s < T_) {
            // ================= layer-0 step s (warp-synchronous) ============
            const int t = s;

            // issue h0[t-1] chunks for this warp's 16 rows
            if (t > 0) {
                const long long inoff = (long long)((t & 1) ^ 1) * B_ * H_;
#pragma unroll
                for (int c = 0; c < 4; c++) {
#pragma unroll
                    for (int i = 0; i < 8; i++) {
                        int idx = lane + i * 32;         // 0..255
                        int r   = idx >> 4;              // 0..15
                        int seg = idx & 15;
                        const __half* src = h0 + inoff
                            + (long long)(wrow0 + r) * H_ + c * 128 + seg * 8;
                        CP_ASYNC16(hsb + (uint32_t)c * HCW_BYTES
                                   + (uint32_t)(r * 136 + seg * 8) * 2, src);
                    }
                    CP_COMMIT();
                }
            }

            // early-issue xp loads (consumed at cell update)
            float2 xpv[4][2];
#pragma unroll
            for (int g = 0; g < 4; g++)
#pragma unroll
                for (int rr = 0; rr < 2; rr++) {
                    int b = wrow0 + r0 + rr * 8;
                    xpv[g][rr] = *(const float2*)&xp0[((size_t)b * T_ + t) * G4_
                                                      + g * H_ + j0 + u0];
                }

#pragma unroll
            for (int g = 0; g < 4; g++)
#pragma unroll
                for (int e = 0; e < 4; e++) acc[g][e] = 0.f;

            if (t > 0) {
                auto consume = [&](int c) {
                    const uint32_t hb = hsb + (uint32_t)c * HCW_BYTES;
#pragma unroll
                    for (int kk2 = 0; kk2 < 8; kk2++) {
                        uint32_t a[4], bf0[4], bf1[4];
                        LDSM_X4(a, hb + (uint32_t)(arow_l * 136 + kk2 * 16 + acol_l) * 2);
                        int kg = c * 8 + kk2;
                        uint32_t bd = smb + (uint32_t)(brow_l * WS0_STR
                                                       + kg * 16 + bcol_l) * 2;
                        LDSM_X4(bf0, bd);
                        LDSM_X4(bf1, bd + (uint32_t)(16 * WS0_STR) * 2);
                        mma_f16(acc[0], a, bf0);
                        mma_f16(acc[1], a, bf0 + 2);
                        mma_f16(acc[2], a, bf1);
                        mma_f16(acc[3], a, bf1 + 2);
                    }
                };
                CP_WAIT(3); __syncwarp(); consume(0);
                CP_WAIT(2); __syncwarp(); consume(1);
                CP_WAIT(1); __syncwarp(); consume(2);
                CP_WAIT(0); __syncwarp(); consume(3);
            }

            // cell update in registers
            const long long outoff = (long long)(t & 1) * B_ * H_;
#pragma unroll
            for (int e = 0; e < 4; e++) {
                int rr = e >> 1, uu = e & 1;
                float gi = xpv[0][rr].x * (uu ? 0.f : 1.f) + (uu ? xpv[0][rr].y : 0.f) + acc[0][e];
                // simpler: select component
                gi = (uu ? xpv[0][rr].y : xpv[0][rr].x) + acc[0][e];
                float gf = (uu ? xpv[1][rr].y : xpv[1][rr].x) + acc[1][e];
                float gc = (uu ? xpv[2][rr].y : xpv[2][rr].x) + acc[2][e];
                float go = (uu ? xpv[3][rr].y : xpv[3][rr].x) + acc[3][e];
                float i_ = sigmoid_fast(gi);
                float f_ = sigmoid_fast(gf);
                float g_ = tanh_fast(gc);
                float o_ = sigmoid_fast(go);
                float cn = f_ * cst[e] + i_ * g_;
                cst[e] = cn;
                int b = wrow0 + r0 + rr * 8;
                h0[outoff + (long long)b * H_ + j0 + u0 + uu] =
                    __float2half(o_ * tanh_fast(cn));
            }
        } else if (!isL0 && s >= 1) {
            // ================= layer-1 step t = s-1 (warp-synchronous) ======
            const int t = s - 1;
            const long long in0 = (long long)(t & 1) * B_ * H_;         // h0[t]
            const long long in1 = (long long)((t & 1) ^ 1) * B_ * H_;   // h1[t-1]
            const int nch = (t == 0) ? 4 : 8;

            // issue all chunks for this warp's rows
#pragma unroll
            for (int c = 0; c < 8; c++) {
                if (c >= nch) break;
                const __half* sh = (c < 4) ? (h0 + in0) : (h1 + in1);
                int coff = (c < 4) ? c * 128 : (c - 4) * 128;
#pragma unroll
                for (int i = 0; i < 8; i++) {
                    int idx = lane + i * 32;
                    int r   = idx >> 4;
                    int seg = idx & 15;
                    const __half* src = sh + (long long)(wrow0 + r) * H_ + coff + seg * 8;
                    CP_ASYNC16(hsb + (uint32_t)c * HCW_BYTES
                               + (uint32_t)(r * 136 + seg * 8) * 2, src);
                }
                CP_COMMIT();
            }

#pragma unroll
            for (int g = 0; g < 4; g++)
#pragma unroll
                for (int e = 0; e < 4; e++) acc[g][e] = 0.f;

            auto consume = [&](int c) {
                const uint32_t hb = hsb + (uint32_t)c * HCW_BYTES;
#pragma unroll
                for (int kk2 = 0; kk2 < 8; kk2++) {
                    uint32_t a[4], bf0[4], bf1[4];
                    LDSM_X4(a, hb + (uint32_t)(arow_l * 136 + kk2 * 16 + acol_l) * 2);
                    int kg = c * 8 + kk2;
                    uint32_t bd = smb + (uint32_t)(brow_l * WS1_STR
                                                   + kg * 16 + bcol_l) * 2;
                    LDSM_X4(bf0, bd);
                    LDSM_X4(bf1, bd + (uint32_t)(16 * WS1_STR) * 2);
                    mma_f16(acc[0], a, bf0);
                    mma_f16(acc[1], a, bf0 + 2);
                    mma_f16(acc[2], a, bf1);
                    mma_f16(acc[3], a, bf1 + 2);
                }
            };
            if (nch == 8) {
                CP_WAIT(7); __syncwarp(); consume(0);
                CP_WAIT(6); __syncwarp(); consume(1);
                CP_WAIT(5); __syncwarp(); consume(2);
                CP_WAIT(4); __syncwarp(); consume(3);
                CP_WAIT(3); __syncwarp(); consume(4);
                CP_WAIT(2); __syncwarp(); consume(5);
                CP_WAIT(1); __syncwarp(); consume(6);
                CP_WAIT(0); __syncwarp(); consume(7);
            } else {
                CP_WAIT(3); __syncwarp(); consume(0);
                CP_WAIT(2); __syncwarp(); consume(1);
                CP_WAIT(1); __syncwarp(); consume(2);
                CP_WAIT(0); __syncwarp(); consume(3);
            }

            const long long outoff = (long long)(t & 1) * B_ * H_;
#pragma unroll
            for (int e = 0; e < 4; e++) {
                int rr = e >> 1, uu = e & 1;
                float gi = bias_v[0][uu] + acc[0][e];
                float gf = bias_v[1][uu] + acc[1][e];
                float gc = bias_v[2][uu] + acc[2][e];
                float go = bias_v[3][uu] + acc[3][e];
                float i_ = sigmoid_fast(gi);
                float f_ = sigmoid_fast(gf);
                float g_ = tanh_fast(gc);
                float o_ = sigmoid_fast(go);
                float cn = f_ * cst[e] + i_ * g_;
                cst[e] = cn;
                int b = wrow0 + r0 + rr * 8;
                h1[outoff + (long long)b * H_ + j0 + u0 + uu] =
                    __float2half(o_ * tanh_fast(cn));
            }
        }

        // ---- two-level grid barrier between stages ----
        if (s < T_) {
            __syncthreads();
            if (tx == 0) {
                asm volatile("red.release.gpu.global.add.u32 [%0], %1;"
                             :: "l"(bars + grp * 64), "r"(1u) : "memory");
            }
            if (tx < NGRP) {
                unsigned target = (unsigned)(s + 1) * 16u;
                unsigned* p = bars + tx * 64;
                unsigned v;
                do {
                    asm volatile("ld.acquire.gpu.global.u32 %0, [%1];"
                                 : "=r"(v) : "l"(p) : "memory");
                } while (v < target);
            }
            __syncthreads();
        }
    }
}

// ---------------------------------------------------------------------------
// Final FC on fp16 h
// ---------------------------------------------------------------------------
__global__ __launch_bounds__(128) void fc_kernel(
    const __half* __restrict__ h, const float* __restrict__ Wfc,
    const float* __restrict__ bfc, float* __restrict__ out)
{
    __shared__ float hrow[H_];
    int b = blockIdx.x;
    for (int k = threadIdx.x; k < H_; k += 128)
        hrow[k] = __half2float(h[b * H_ + k]);
    __syncthreads();

    int o = threadIdx.x;
    float s = bfc[o];
    const float4* w4 = reinterpret_cast<const float4*>(Wfc + (size_t)o * H_);
    const float4* h4 = reinterpret_cast<const float4*>(hrow);
#pragma unroll 4
    for (int k = 0; k < H_ / 4; k++) {
        float4 w = w4[k];
        float4 hh = h4[k];
        s += w.x * hh.x + w.y * hh.y + w.z * hh.z + w.w * hh.w;
    }
    out[b * OUT_ + o] = s;
}

// ---------------------------------------------------------------------------
extern "C" void kernel_launch(void* const* d_in, const int* in_sizes, int n_in,
                              void* d_out, int out_size)
{
    const float* x     = (const float*)d_in[0];
    const float* W_ih0 = (const float*)d_in[1];
    const float* W_hh0 = (const float*)d_in[2];
    const float* b_ih0 = (const float*)d_in[3];
    const float* b_hh0 = (const float*)d_in[4];
    const float* W_ih1 = (const float*)d_in[5];
    const float* W_hh1 = (const float*)d_in[6];
    const float* b_ih1 = (const float*)d_in[7];
    const float* b_hh1 = (const float*)d_in[8];
    const float* W_fc  = (const float*)d_in[9];
    const float* b_fc  = (const float*)d_in[10];
    float* out = (float*)d_out;

    float* xp;
    unsigned* bars;
    __nv_bfloat16 *xhi, *xlo, *whi, *wlo;
    __half *h0, *h1;
    cudaGetSymbolAddress((void**)&xp,   g_xp);
    cudaGetSymbolAddress((void**)&bars, g_bars);
    cudaGetSymbolAddress((void**)&xhi,  g_Xhi);
    cudaGetSymbolAddress((void**)&xlo,  g_Xlo);
    cudaGetSymbolAddress((void**)&whi,  g_Whi);
    cudaGetSymbolAddress((void**)&wlo,  g_Wlo);
    cudaGetSymbolAddress((void**)&h0,   g_h0);
    cudaGetSymbolAddress((void**)&h1,   g_h1);

    cudaFuncSetAttribute(gemm_mma_kernel,
                         cudaFuncAttributeMaxDynamicSharedMemorySize, GEMM_SMEM_BYTES);
    cudaFuncSetAttribute(lstm_fused_kernel,
                         cudaFuncAttributeMaxDynamicSharedMemorySize, FUSED_SMEM);

    dim3 mma_grid(G4_ / 128, M_ / 128);   // (16, 256)

    // layer-0 xp GEMM (K=128); first split also resets the barrier counters
    {
        int nA = M_ * IN_;
        int nW = G4_ * IN_;
        split_bf16_kernel<<<(nA + 255) / 256, 256>>>(x, xhi, xlo, nA, bars);
        split_bf16_kernel<<<(nW + 255) / 256, 256>>>(W_ih0, whi, wlo, nW, nullptr);
        gemm_mma_kernel<<<mma_grid, 256, GEMM_SMEM_BYTES>>>(xhi, xlo, whi, wlo,
                                                            b_ih0, b_hh0, xp, IN_);
    }

    // fused two-layer recurrence (warp-synchronous steps)
    lstm_fused_kernel<<<FBLK, FTHR, FUSED_SMEM>>>(
        xp, W_hh0, W_ih1, W_hh1, b_ih1, b_hh1, h0, h1, bars);

    // final FC on h1[t=511] (parity 1)
    fc_kernel<<<B_, 128>>>(h1 + (size_t)B_ * H_, W_fc, b_fc, out);
}

// round 16
// speedup vs baseline: 1.5558x; 1.1148x over previous
#include <cuda_runtime.h>
#include <cuda_fp16.h>
#include <math.h>
#include <stdint.h>

#define B_   64
#define T_   512
#define IN_  128
#define H_   512
#define G4_  2048
#define OUT_ 128
#define M_   (B_ * T_)   // 32768

#define FBLK 128    // 64 layer-0 + 64 layer-1 blocks
#define FTHR 128    // 4 warps per block (warp = 16 batch rows x 32 gate cols)
#define NGRP 8      // barrier groups (16 blocks each)

// ---------------- scratch (static device memory; no allocs) ----------------
__device__ unsigned int g_bars[NGRP * 64];          // group counters, 256B apart
__device__ __half g_x16[(size_t)M_ * IN_];          // x in fp16
__device__ __half g_h0[2 * B_ * H_];                // layer-0 h ping-pong (fp16)
__device__ __half g_h1[2 * B_ * H_];                // layer-1 h ping-pong (fp16)

// ======================= helpers ==============================
__device__ __forceinline__ uint32_t smem_u32(const void* p) {
    uint32_t a;
    asm("{ .reg .u64 t; cvta.to.shared.u64 t, %1; cvt.u32.u64 %0, t; }"
        : "=r"(a) : "l"(p));
    return a;
}

#define LDSM_X4(r, addr) \
    asm volatile("ldmatrix.sync.aligned.m8n8.x4.shared.b16 {%0,%1,%2,%3}, [%4];" \
        : "=r"((r)[0]), "=r"((r)[1]), "=r"((r)[2]), "=r"((r)[3]) : "r"(addr))

__device__ __forceinline__ void mma_f16(float* d, const uint32_t* a, const uint32_t* b) {
    asm volatile("mma.sync.aligned.m16n8k16.row.col.f32.f16.f16.f32 "
        "{%0,%1,%2,%3}, {%4,%5,%6,%7}, {%8,%9}, {%0,%1,%2,%3};"
        : "+f"(d[0]), "+f"(d[1]), "+f"(d[2]), "+f"(d[3])
        : "r"(a[0]), "r"(a[1]), "r"(a[2]), "r"(a[3]), "r"(b[0]), "r"(b[1]));
}

#define CP_ASYNC16(dst, src) \
    asm volatile("cp.async.cg.shared.global [%0], [%1], 16;" :: "r"(dst), "l"(src))
#define CP_COMMIT() asm volatile("cp.async.commit_group;" ::: "memory")
#define CP_WAIT(n)  asm volatile("cp.async.wait_group %0;" :: "n"(n) : "memory")

__device__ __forceinline__ float sigmoid_fast(float x) {
    float e, r;
    asm("ex2.approx.f32 %0, %1;" : "=f"(e) : "f"(-1.4426950408889634f * x));
    asm("rcp.approx.f32 %0, %1;" : "=f"(r) : "f"(1.f + e));
    return r;
}
__device__ __forceinline__ float tanh_fast(float x) {
    float y;
    asm("tanh.approx.f32 %0, %1;" : "=f"(y) : "f"(x));
    return y;
}

// ---------------------------------------------------------------------------
// x fp32 -> fp16 convert; also resets the barrier counters
// ---------------------------------------------------------------------------
__global__ __launch_bounds__(256) void convert_x_kernel(
    const float* __restrict__ in, __half* __restrict__ out, int n,
    unsigned* bar_reset)
{
    if (bar_reset && blockIdx.x == 0 && threadIdx.x < NGRP)
        bar_reset[threadIdx.x * 64] = 0u;
    int i = blockIdx.x * 256 + threadIdx.x;
    if (i < n) out[i] = __float2half(in[i]);
}

// ---------------------------------------------------------------------------
// FUSED two-layer persistent LSTM — warp-synchronous steps, NO front GEMM.
// Blocks 0..63 (L0): resident W_hh0 (32x520) + W_ih0 (32x136) slices;
//   per stage: warp stages its 16 rows of x[:,t,:] (chunk 0, FULL 16x128
//   tile: 256 vec16) + 4 chunks of h0[t-1]; gates = x@W_ih0^T + h@W_hh0^T
//   + bias, all in registers.
// Blocks 64..127 (L1): resident [W_ih1;W_hh1]; 8 chunks of [h0[t];h1[t-1]].
// Cell state in registers; only the inter-block barrier block-syncs.
// ---------------------------------------------------------------------------
#define WS0_STR   520
#define WIH_OFF   33280u            // W_ih0 slice, stride 136 (8704 B)
#define WIH_STR   136
#define HS0_OFF   41984u            // L0 staging: 5 chunks/warp
#define HCW_BYTES 4352u             // 16*136*2 per chunk per warp
#define W0_STAGE  21760u            // 5 chunks
#define WS1_STR   1048
#define HS1_OFF   67072u            // L1 staging: 8 chunks/warp
#define W1_STAGE  34816u
#define FUSED_SMEM 206336

__global__ __launch_bounds__(FTHR, 1) void lstm_fused_kernel(
    const __half* __restrict__ x16,
    const float* __restrict__ Whh0, const float* __restrict__ Wih0,
    const float* __restrict__ b_ih0, const float* __restrict__ b_hh0,
    const float* __restrict__ Wih1, const float* __restrict__ Whh1,
    const float* __restrict__ b_ih1, const float* __restrict__ b_hh1,
    __half* __restrict__ h0, __half* __restrict__ h1,
    unsigned* __restrict__ bars)
{
    extern __shared__ char sm8[];
    const int tx   = threadIdx.x;
    const int wid  = tx >> 5;
    const int lane = tx & 31;
    const bool isL0 = blockIdx.x < 64;
    const int j0   = (blockIdx.x & 63) * 8;
    const int grp  = blockIdx.x >> 4;

    const uint32_t smb = smem_u32(sm8);
    __half* ws = (__half*)sm8;

    // fragment addressing
    const int arow_l = (lane & 7) + ((lane >> 3) & 1) * 8;
    const int acol_l = (lane >> 4) * 8;
    const int brow_l = ((lane >> 4) & 1) * 8 + (lane & 7);
    const int bcol_l = ((lane >> 3) & 1) * 8;

    // cell ownership (m16n8k16 D fragment)
    const int r0 = lane >> 2;
    const int u0 = (lane & 3) * 2;

    float bias_v[4][2];

    if (isL0) {
        // W_hh0 slice -> fp16 (stride 520)
        for (int i = 0; i < 128; i++) {
            int idx = tx + i * 128;
            int cc = idx >> 9, k = idx & 511;
            int gg = cc >> 3, u = cc & 7;
            ws[cc * WS0_STR + k] =
                __float2half(Whh0[(size_t)(gg * H_ + j0 + u) * H_ + k]);
        }
        // W_ih0 slice -> fp16 (stride 136)
        for (int i = 0; i < 32; i++) {
            int idx = tx + i * 128;
            int cc = idx >> 7, k = idx & 127;
            int gg = cc >> 3, u = cc & 7;
            ws[(WIH_OFF >> 1) + cc * WIH_STR + k] =
                __float2half(Wih0[(size_t)(gg * H_ + j0 + u) * IN_ + k]);
        }
#pragma unroll
        for (int g = 0; g < 4; g++) {
            bias_v[g][0] = b_ih0[g * H_ + j0 + u0]     + b_hh0[g * H_ + j0 + u0];
            bias_v[g][1] = b_ih0[g * H_ + j0 + u0 + 1] + b_hh0[g * H_ + j0 + u0 + 1];
        }
    } else {
        // [W_ih1 ; W_hh1] slice -> fp16 (stride 1048)
        for (int i = 0; i < 256; i++) {
            int idx = tx + i * 128;
            int cc = idx >> 10, k = idx & 1023;
            int gg = cc >> 3, u = cc & 7;
            size_t row = (size_t)(gg * H_ + j0 + u) * H_;
            float w = (k < 512) ? Wih1[row + k] : Whh1[row + k - 512];
            ws[cc * WS1_STR + k] = __float2half(w);
        }
#pragma unroll
        for (int g = 0; g < 4; g++) {
            bias_v[g][0] = b_ih1[g * H_ + j0 + u0]     + b_hh1[g * H_ + j0 + u0];
            bias_v[g][1] = b_ih1[g * H_ + j0 + u0 + 1] + b_hh1[g * H_ + j0 + u0 + 1];
        }
    }
    __syncthreads();

    float acc[4][4];
    float cst[4];
#pragma unroll
    for (int e = 0; e < 4; e++) cst[e] = 0.f;

    const uint32_t hsb = smb + (isL0 ? HS0_OFF : HS1_OFF)
                       + (uint32_t)wid * (isL0 ? W0_STAGE : W1_STAGE);
    const int wrow0 = wid * 16;

    for (int s = 0; s <= T_; s++) {
        if (isL0 && s < T_) {
            // ================= layer-0 step s =================
            const int t = s;

            // chunk 0: x[wrow0.., t, :] fp16 — FULL 16x128 tile (256 vec16)
#pragma unroll
            for (int i = 0; i < 8; i++) {
                int idx = lane + i * 32;         // 0..255
                int r   = idx >> 4;              // 0..15
                int seg = idx & 15;              // 0..15 -> cols 0..127
                const __half* src = x16 + ((size_t)(wrow0 + r) * T_ + t) * IN_ + seg * 8;
                CP_ASYNC16(hsb + (uint32_t)(r * 136 + seg * 8) * 2, src);
            }
            CP_COMMIT();

            // chunks 1..4: h0[t-1]
            if (t > 0) {
                const long long inoff = (long long)((t & 1) ^ 1) * B_ * H_;
#pragma unroll
                for (int c = 0; c < 4; c++) {
#pragma unroll
                    for (int i = 0; i < 8; i++) {
                        int idx = lane + i * 32;
                        int r   = idx >> 4;
                        int seg = idx & 15;
                        const __half* src = h0 + inoff
                            + (long long)(wrow0 + r) * H_ + c * 128 + seg * 8;
                        CP_ASYNC16(hsb + (uint32_t)(1 + c) * HCW_BYTES
                                   + (uint32_t)(r * 136 + seg * 8) * 2, src);
                    }
                    CP_COMMIT();
                }
            }

#pragma unroll
            for (int g = 0; g < 4; g++)
#pragma unroll
                for (int e = 0; e < 4; e++) acc[g][e] = 0.f;

            // consume x-projection (K=128, B = W_ih0 slice)
            if (t > 0) { CP_WAIT(4); } else { CP_WAIT(0); }
            __syncwarp();
#pragma unroll
            for (int kk2 = 0; kk2 < 8; kk2++) {
                uint32_t a[4], bf0[4], bf1[4];
                LDSM_X4(a, hsb + (uint32_t)(arow_l * 136 + kk2 * 16 + acol_l) * 2);
                uint32_t bd = smb + WIH_OFF
                            + (uint32_t)(brow_l * WIH_STR + kk2 * 16 + bcol_l) * 2;
                LDSM_X4(bf0, bd);
                LDSM_X4(bf1, bd + (uint32_t)(16 * WIH_STR) * 2);
                mma_f16(acc[0], a, bf0);
                mma_f16(acc[1], a, bf0 + 2);
                mma_f16(acc[2], a, bf1);
                mma_f16(acc[3], a, bf1 + 2);
            }

            // consume h chunks (K=512, B = W_hh0 slice)
            if (t > 0) {
                auto consume = [&](int c) {
                    const uint32_t hb = hsb + (uint32_t)(1 + c) * HCW_BYTES;
#pragma unroll
                    for (int kk2 = 0; kk2 < 8; kk2++) {
                        uint32_t a[4], bf0[4], bf1[4];
                        LDSM_X4(a, hb + (uint32_t)(arow_l * 136 + kk2 * 16 + acol_l) * 2);
                        int kg = c * 8 + kk2;
                        uint32_t bd = smb + (uint32_t)(brow_l * WS0_STR
                                                       + kg * 16 + bcol_l) * 2;
                        LDSM_X4(bf0, bd);
                        LDSM_X4(bf1, bd + (uint32_t)(16 * WS0_STR) * 2);
                        mma_f16(acc[0], a, bf0);
                        mma_f16(acc[1], a, bf0 + 2);
                        mma_f16(acc[2], a, bf1);
                        mma_f16(acc[3], a, bf1 + 2);
                    }
                };
                CP_WAIT(3); __syncwarp(); consume(0);
                CP_WAIT(2); __syncwarp(); consume(1);
                CP_WAIT(1); __syncwarp(); consume(2);
                CP_WAIT(0); __syncwarp(); consume(3);
            }

            // register cell update
            const long long outoff = (long long)(t & 1) * B_ * H_;
#pragma unroll
            for (int e = 0; e < 4; e++) {
                int rr = e >> 1, uu = e & 1;
                float gi = bias_v[0][uu] + acc[0][e];
                float gf = bias_v[1][uu] + acc[1][e];
                float gc = bias_v[2][uu] + acc[2][e];
                float go = bias_v[3][uu] + acc[3][e];
                float i_ = sigmoid_fast(gi);
                float f_ = sigmoid_fast(gf);
                float g_ = tanh_fast(gc);
                float o_ = sigmoid_fast(go);
                float cn = f_ * cst[e] + i_ * g_;
                cst[e] = cn;
                int b = wrow0 + r0 + rr * 8;
                h0[outoff + (long long)b * H_ + j0 + u0 + uu] =
                    __float2half(o_ * tanh_fast(cn));
            }
        } else if (!isL0 && s >= 1) {
            // ================= layer-1 step t = s-1 =================
            const int t = s - 1;
            const long long in0 = (long long)(t & 1) * B_ * H_;
            const long long in1 = (long long)((t & 1) ^ 1) * B_ * H_;
            const int nch = (t == 0) ? 4 : 8;

#pragma unroll
            for (int c = 0; c < 8; c++) {
                if (c >= nch) break;
                const __half* sh = (c < 4) ? (h0 + in0) : (h1 + in1);
                int coff = (c < 4) ? c * 128 : (c - 4) * 128;
#pragma unroll
                for (int i = 0; i < 8; i++) {
                    int idx = lane + i * 32;
                    int r   = idx >> 4;
                    int seg = idx & 15;
                    const __half* src = sh + (long long)(wrow0 + r) * H_ + coff + seg * 8;
                    CP_ASYNC16(hsb + (uint32_t)c * HCW_BYTES
                               + (uint32_t)(r * 136 + seg * 8) * 2, src);
                }
                CP_COMMIT();
            }

#pragma unroll
            for (int g = 0; g < 4; g++)
#pragma unroll
                for (int e = 0; e < 4; e++) acc[g][e] = 0.f;

            auto consume = [&](int c) {
                const uint32_t hb = hsb + (uint32_t)c * HCW_BYTES;
#pragma unroll
                for (int kk2 = 0; kk2 < 8; kk2++) {
                    uint32_t a[4], bf0[4], bf1[4];
                    LDSM_X4(a, hb + (uint32_t)(arow_l * 136 + kk2 * 16 + acol_l) * 2);
                    int kg = c * 8 + kk2;
                    uint32_t bd = smb + (uint32_t)(brow_l * WS1_STR
                                                   + kg * 16 + bcol_l) * 2;
                    LDSM_X4(bf0, bd);
                    LDSM_X4(bf1, bd + (uint32_t)(16 * WS1_STR) * 2);
                    mma_f16(acc[0], a, bf0);
                    mma_f16(acc[1], a, bf0 + 2);
                    mma_f16(acc[2], a, bf1);
                    mma_f16(acc[3], a, bf1 + 2);
                }
            };
            if (nch == 8) {
                CP_WAIT(7); __syncwarp(); consume(0);
                CP_WAIT(6); __syncwarp(); consume(1);
                CP_WAIT(5); __syncwarp(); consume(2);
                CP_WAIT(4); __syncwarp(); consume(3);
                CP_WAIT(3); __syncwarp(); consume(4);
                CP_WAIT(2); __syncwarp(); consume(5);
                CP_WAIT(1); __syncwarp(); consume(6);
                CP_WAIT(0); __syncwarp(); consume(7);
            } else {
                CP_WAIT(3); __syncwarp(); consume(0);
                CP_WAIT(2); __syncwarp(); consume(1);
                CP_WAIT(1); __syncwarp(); consume(2);
                CP_WAIT(0); __syncwarp(); consume(3);
            }

            const long long outoff = (long long)(t & 1) * B_ * H_;
#pragma unroll
            for (int e = 0; e < 4; e++) {
                int rr = e >> 1, uu = e & 1;
                float gi = bias_v[0][uu] + acc[0][e];
                float gf = bias_v[1][uu] + acc[1][e];
                float gc = bias_v[2][uu] + acc[2][e];
                float go = bias_v[3][uu] + acc[3][e];
                float i_ = sigmoid_fast(gi);
                float f_ = sigmoid_fast(gf);
                float g_ = tanh_fast(gc);
                float o_ = sigmoid_fast(go);
                float cn = f_ * cst[e] + i_ * g_;
                cst[e] = cn;
                int b = wrow0 + r0 + rr * 8;
                h1[outoff + (long long)b * H_ + j0 + u0 + uu] =
                    __float2half(o_ * tanh_fast(cn));
            }
        }

        // ---- two-level grid barrier between stages ----
        if (s < T_) {
            __syncthreads();
            if (tx == 0) {
                asm volatile("red.release.gpu.global.add.u32 [%0], %1;"
                             :: "l"(bars + grp * 64), "r"(1u) : "memory");
            }
            if (tx < NGRP) {
                unsigned target = (unsigned)(s + 1) * 16u;
                unsigned* p = bars + tx * 64;
                unsigned v;
                do {
                    asm volatile("ld.acquire.gpu.global.u32 %0, [%1];"
                                 : "=r"(v) : "l"(p) : "memory");
                } while (v < target);
            }
            __syncthreads();
        }
    }
}

// ---------------------------------------------------------------------------
// Final FC on fp16 h
// ---------------------------------------------------------------------------
__global__ __launch_bounds__(128) void fc_kernel(
    const __half* __restrict__ h, const float* __restrict__ Wfc,
    const float* __restrict__ bfc, float* __restrict__ out)
{
    __shared__ float hrow[H_];
    int b = blockIdx.x;
    for (int k = threadIdx.x; k < H_; k += 128)
        hrow[k] = __half2float(h[b * H_ + k]);
    __syncthreads();

    int o = threadIdx.x;
    float s = bfc[o];
    const float4* w4 = reinterpret_cast<const float4*>(Wfc + (size_t)o * H_);
    const float4* h4 = reinterpret_cast<const float4*>(hrow);
#pragma unroll 4
    for (int k = 0; k < H_ / 4; k++) {
        float4 w = w4[k];
        float4 hh = h4[k];
        s += w.x * hh.x + w.y * hh.y + w.z * hh.z + w.w * hh.w;
    }
    out[b * OUT_ + o] = s;
}

// ---------------------------------------------------------------------------
extern "C" void kernel_launch(void* const* d_in, const int* in_sizes, int n_in,
                              void* d_out, int out_size)
{
    const float* x     = (const float*)d_in[0];
    const float* W_ih0 = (const float*)d_in[1];
    const float* W_hh0 = (const float*)d_in[2];
    const float* b_ih0 = (const float*)d_in[3];
    const float* b_hh0 = (const float*)d_in[4];
    const float* W_ih1 = (const float*)d_in[5];
    const float* W_hh1 = (const float*)d_in[6];
    const float* b_ih1 = (const float*)d_in[7];
    const float* b_hh1 = (const float*)d_in[8];
    const float* W_fc  = (const float*)d_in[9];
    const float* b_fc  = (const float*)d_in[10];
    float* out = (float*)d_out;

    unsigned* bars;
    __half *x16, *h0, *h1;
    cudaGetSymbolAddress((void**)&bars, g_bars);
    cudaGetSymbolAddress((void**)&x16,  g_x16);
    cudaGetSymbolAddress((void**)&h0,   g_h0);
    cudaGetSymbolAddress((void**)&h1,   g_h1);

    cudaFuncSetAttribute(lstm_fused_kernel,
                         cudaFuncAttributeMaxDynamicSharedMemorySize, FUSED_SMEM);

    // convert x to fp16 (also resets barrier counters)
    int nX = M_ * IN_;
    convert_x_kernel<<<(nX + 255) / 256, 256>>>(x, x16, nX, bars);

    // fused two-layer recurrence (front GEMM folded into layer-0 steps)
    lstm_fused_kernel<<<FBLK, FTHR, FUSED_SMEM>>>(
        x16, W_hh0, W_ih0, b_ih0, b_hh0,
        W_ih1, W_hh1, b_ih1, b_hh1, h0, h1, bars);

    // final FC on h1[t=511] (parity 1)
    fc_kernel<<<B_, 128>>>(h1 + (size_t)B_ * H_, W_fc, b_fc, out);
}